// round 1
// baseline (speedup 1.0000x reference)
#include <cuda_runtime.h>

#define SEQ    2048
#define DIM    4096
#define NH     32
#define NKV    8
#define HD     128
#define KV_DIM 1024   // NKV * HD
#define BQ     64
#define BK     64

// Scratch (static device memory — no runtime allocation)
__device__ float g_Q[SEQ * DIM];
__device__ float g_K[SEQ * KV_DIM];
__device__ float g_V[SEQ * KV_DIM];
__device__ float g_O[SEQ * DIM];

// ---------------------------------------------------------------------------
// SGEMM (NT): C[M,N] = A[M,K] @ B[N,K]^T   (all row-major fp32)
// 128x128 block tile, K-step 8, 256 threads, 8x8 micro-tile, double-buffered.
// ---------------------------------------------------------------------------
__global__ __launch_bounds__(256, 2)
void sgemm_nt(const float* __restrict__ A, const float* __restrict__ B,
              float* __restrict__ C, int M, int N, int K) {
    __shared__ float As[2][8][128];
    __shared__ float Bs[2][8][128];

    int tid = threadIdx.x;
    int m0 = blockIdx.y * 128;
    int n0 = blockIdx.x * 128;

    int lrow = tid >> 1;          // 0..127
    int lcol = (tid & 1) << 2;    // 0 or 4

    const float* Ap = A + (long)(m0 + lrow) * K + lcol;
    const float* Bp = B + (long)(n0 + lrow) * K + lcol;

    float4 ar = *(const float4*)Ap;
    float4 br = *(const float4*)Bp;
    As[0][lcol + 0][lrow] = ar.x; As[0][lcol + 1][lrow] = ar.y;
    As[0][lcol + 2][lrow] = ar.z; As[0][lcol + 3][lrow] = ar.w;
    Bs[0][lcol + 0][lrow] = br.x; Bs[0][lcol + 1][lrow] = br.y;
    Bs[0][lcol + 2][lrow] = br.z; Bs[0][lcol + 3][lrow] = br.w;
    __syncthreads();

    int tx = tid & 15;
    int ty = tid >> 4;

    float acc[8][8];
#pragma unroll
    for (int i = 0; i < 8; ++i)
#pragma unroll
        for (int j = 0; j < 8; ++j) acc[i][j] = 0.0f;

    int nk = K >> 3;
    for (int t = 0; t < nk; ++t) {
        int cur = t & 1;
        if (t + 1 < nk) {
            ar = *(const float4*)(Ap + (t + 1) * 8);
            br = *(const float4*)(Bp + (t + 1) * 8);
        }
#pragma unroll
        for (int kk = 0; kk < 8; ++kk) {
            float4 a0 = *(const float4*)&As[cur][kk][ty * 4];
            float4 a1 = *(const float4*)&As[cur][kk][64 + ty * 4];
            float4 b0 = *(const float4*)&Bs[cur][kk][tx * 4];
            float4 b1 = *(const float4*)&Bs[cur][kk][64 + tx * 4];
            float av[8] = {a0.x, a0.y, a0.z, a0.w, a1.x, a1.y, a1.z, a1.w};
            float bv[8] = {b0.x, b0.y, b0.z, b0.w, b1.x, b1.y, b1.z, b1.w};
#pragma unroll
            for (int i = 0; i < 8; ++i)
#pragma unroll
                for (int j = 0; j < 8; ++j) acc[i][j] += av[i] * bv[j];
        }
        if (t + 1 < nk) {
            int nxt = cur ^ 1;
            As[nxt][lcol + 0][lrow] = ar.x; As[nxt][lcol + 1][lrow] = ar.y;
            As[nxt][lcol + 2][lrow] = ar.z; As[nxt][lcol + 3][lrow] = ar.w;
            Bs[nxt][lcol + 0][lrow] = br.x; Bs[nxt][lcol + 1][lrow] = br.y;
            Bs[nxt][lcol + 2][lrow] = br.z; Bs[nxt][lcol + 3][lrow] = br.w;
        }
        __syncthreads();
    }

#pragma unroll
    for (int i = 0; i < 8; ++i) {
        int row = m0 + ((i < 4) ? (ty * 4 + i) : (64 + ty * 4 + (i - 4)));
        float4 v0 = make_float4(acc[i][0], acc[i][1], acc[i][2], acc[i][3]);
        float4 v1 = make_float4(acc[i][4], acc[i][5], acc[i][6], acc[i][7]);
        *(float4*)&C[(long)row * N + n0 + tx * 4]      = v0;
        *(float4*)&C[(long)row * N + n0 + 64 + tx * 4] = v1;
    }
}

// ---------------------------------------------------------------------------
// RoPE (interleaved pairs), in place on [SEQ, nheads*HD]
// ---------------------------------------------------------------------------
__global__ void rope_kernel(float* __restrict__ X,
                            const float* __restrict__ cs,
                            const float* __restrict__ sn,
                            int nheads) {
    int pps = nheads * (HD / 2);      // pairs per sequence position
    int total = SEQ * pps;
    int idx = blockIdx.x * blockDim.x + threadIdx.x;
    if (idx >= total) return;
    int s = idx / pps;
    int r = idx - s * pps;
    int p = r & 63;                   // pair index within head
    float2 v = ((float2*)X)[(long)s * pps + r];
    float c  = cs[s * 64 + p];
    float si = sn[s * 64 + p];
    float2 o;
    o.x = v.x * c - v.y * si;
    o.y = v.x * si + v.y * c;
    ((float2*)X)[(long)s * pps + r] = o;
}

// ---------------------------------------------------------------------------
// Flash attention (fp32, causal, GQA 4:1). One block = (head, 64-query tile).
// smem: Qs[d][i] 128x64, Ks[d][j] 128x64, Vs[j][d] 64x128, St[j][i] 64x64,
//       m/l/alpha rows.
// ---------------------------------------------------------------------------
#define ATTN_SMEM_FLOATS (128 * 64 + 128 * 64 + 64 * 128 + 64 * 64 + 3 * 64)

__global__ __launch_bounds__(256, 1)
void attn_kernel(const float* __restrict__ Q, const float* __restrict__ Kb,
                 const float* __restrict__ Vb, float* __restrict__ O) {
    extern __shared__ float smf[];
    float* Qs  = smf;                 // [128][64]  (d-major)
    float* Ks  = Qs + 128 * 64;       // [128][64]  (d-major)
    float* Vs  = Ks + 128 * 64;       // [64][128]  (row-major)
    float* St  = Vs + 64 * 128;       // [64][64]   St[j][i]
    float* mrow = St + 64 * 64;
    float* lrow = mrow + 64;
    float* arow = lrow + 64;

    int tid = threadIdx.x;
    int h   = blockIdx.y;
    int q0  = blockIdx.x * BQ;
    int kvh = h >> 2;
    const float scale = 0.08838834764831845f;   // 1/sqrt(128)
    const float NEG_INF = __int_as_float(0xff800000);

    // Load Q tile (d-major in smem)
    for (int r = tid; r < BQ * (HD / 4); r += 256) {
        int i = r >> 5;
        int c = r & 31;
        float4 v = *(const float4*)&Q[(long)(q0 + i) * DIM + h * HD + c * 4];
        Qs[(c * 4 + 0) * 64 + i] = v.x;
        Qs[(c * 4 + 1) * 64 + i] = v.y;
        Qs[(c * 4 + 2) * 64 + i] = v.z;
        Qs[(c * 4 + 3) * 64 + i] = v.w;
    }
    if (tid < 64) { mrow[tid] = NEG_INF; lrow[tid] = 0.0f; }

    int tx = tid & 15;
    int ty = tid >> 4;

    float o[4][8];
#pragma unroll
    for (int i = 0; i < 4; ++i)
#pragma unroll
        for (int j = 0; j < 8; ++j) o[i][j] = 0.0f;

    int ntile = blockIdx.x + 1;   // causal: kv tiles 0..qtile
    for (int t = 0; t < ntile; ++t) {
        int j0 = t * BK;
        __syncthreads();   // previous readers of Ks/Vs/St done; Qs/m/l ready

        // Load K (d-major) and V (row-major) tiles
        for (int r = tid; r < BK * (HD / 4); r += 256) {
            int j = r >> 5;
            int c = r & 31;
            long gk = (long)(j0 + j) * KV_DIM + kvh * HD + c * 4;
            float4 kv = *(const float4*)&Kb[gk];
            Ks[(c * 4 + 0) * 64 + j] = kv.x;
            Ks[(c * 4 + 1) * 64 + j] = kv.y;
            Ks[(c * 4 + 2) * 64 + j] = kv.z;
            Ks[(c * 4 + 3) * 64 + j] = kv.w;
            float4 vv = *(const float4*)&Vb[gk];
            *(float4*)&Vs[j * 128 + c * 4] = vv;
        }
        __syncthreads();

        // S = Q @ K^T  (4x4 micro-tile per thread)
        float s[4][4];
#pragma unroll
        for (int i = 0; i < 4; ++i)
#pragma unroll
            for (int j = 0; j < 4; ++j) s[i][j] = 0.0f;

#pragma unroll 4
        for (int d = 0; d < HD; ++d) {
            float4 qf = *(const float4*)(Qs + d * 64 + (ty << 2));
            float4 kf = *(const float4*)(Ks + d * 64 + (tx << 2));
            float qa[4] = {qf.x, qf.y, qf.z, qf.w};
            float ka[4] = {kf.x, kf.y, kf.z, kf.w};
#pragma unroll
            for (int ii = 0; ii < 4; ++ii)
#pragma unroll
                for (int jj = 0; jj < 4; ++jj) s[ii][jj] += qa[ii] * ka[jj];
        }

        bool diag = (j0 == q0);
#pragma unroll
        for (int ii = 0; ii < 4; ++ii) {
            int i = ty * 4 + ii;
#pragma unroll
            for (int jj = 0; jj < 4; ++jj) {
                int j = tx * 4 + jj;
                float val = s[ii][jj] * scale;
                if (diag && j > i) val = -1e30f;
                St[j * 64 + i] = val;
            }
        }
        __syncthreads();

        // Online softmax per row (64 threads)
        if (tid < 64) {
            int i = tid;
            float mold = mrow[i];
            float mt = NEG_INF;
            for (int j = 0; j < BK; ++j) mt = fmaxf(mt, St[j * 64 + i]);
            float mn = fmaxf(mold, mt);
            float alpha = __expf(mold - mn);
            float sum = 0.0f;
            for (int j = 0; j < BK; ++j) {
                float p = __expf(St[j * 64 + i] - mn);
                St[j * 64 + i] = p;
                sum += p;
            }
            lrow[i] = lrow[i] * alpha + sum;
            mrow[i] = mn;
            arow[i] = alpha;
        }
        __syncthreads();

        // Rescale running O and accumulate P @ V (4 rows x 8 cols per thread)
        float al[4];
#pragma unroll
        for (int ii = 0; ii < 4; ++ii) al[ii] = arow[ty * 4 + ii];
#pragma unroll
        for (int ii = 0; ii < 4; ++ii)
#pragma unroll
            for (int jj = 0; jj < 8; ++jj) o[ii][jj] *= al[ii];

#pragma unroll 2
        for (int j = 0; j < BK; ++j) {
            float4 pf = *(const float4*)(St + j * 64 + (ty << 2));
            float4 v0 = *(const float4*)(Vs + j * 128 + (tx << 3));
            float4 v1 = *(const float4*)(Vs + j * 128 + (tx << 3) + 4);
            float pa[4] = {pf.x, pf.y, pf.z, pf.w};
            float va[8] = {v0.x, v0.y, v0.z, v0.w, v1.x, v1.y, v1.z, v1.w};
#pragma unroll
            for (int ii = 0; ii < 4; ++ii)
#pragma unroll
                for (int jj = 0; jj < 8; ++jj) o[ii][jj] += pa[ii] * va[jj];
        }
    }

    // Final normalize + store
#pragma unroll
    for (int ii = 0; ii < 4; ++ii) {
        int i = ty * 4 + ii;
        float inv = 1.0f / lrow[i];
        float4 w0 = make_float4(o[ii][0] * inv, o[ii][1] * inv,
                                o[ii][2] * inv, o[ii][3] * inv);
        float4 w1 = make_float4(o[ii][4] * inv, o[ii][5] * inv,
                                o[ii][6] * inv, o[ii][7] * inv);
        long base = (long)(q0 + i) * DIM + h * HD + (tx << 3);
        *(float4*)&O[base]     = w0;
        *(float4*)&O[base + 4] = w1;
    }
}

// ---------------------------------------------------------------------------
// Launcher
// ---------------------------------------------------------------------------
extern "C" void kernel_launch(void* const* d_in, const int* in_sizes, int n_in,
                              void* d_out, int out_size) {
    const float* x  = (const float*)d_in[0];
    const float* wq = (const float*)d_in[1];
    const float* wk = (const float*)d_in[2];
    const float* wv = (const float*)d_in[3];
    const float* wo = (const float*)d_in[4];
    const float* fc = (const float*)d_in[5];
    const float* fs = (const float*)d_in[6];
    // d_in[7] = mask (causal handled analytically)
    float* out = (float*)d_out;

    float *Qp, *Kp, *Vp, *Op;
    cudaGetSymbolAddress((void**)&Qp, g_Q);
    cudaGetSymbolAddress((void**)&Kp, g_K);
    cudaGetSymbolAddress((void**)&Vp, g_V);
    cudaGetSymbolAddress((void**)&Op, g_O);

    const int attn_smem = ATTN_SMEM_FLOATS * (int)sizeof(float);
    cudaFuncSetAttribute(attn_kernel,
                         cudaFuncAttributeMaxDynamicSharedMemorySize, attn_smem);

    // Projections
    sgemm_nt<<<dim3(DIM / 128, SEQ / 128), 256>>>(x, wq, Qp, SEQ, DIM, DIM);
    sgemm_nt<<<dim3(KV_DIM / 128, SEQ / 128), 256>>>(x, wk, Kp, SEQ, KV_DIM, DIM);
    sgemm_nt<<<dim3(KV_DIM / 128, SEQ / 128), 256>>>(x, wv, Vp, SEQ, KV_DIM, DIM);

    // RoPE on Q and K
    int qpairs = SEQ * NH * (HD / 2);
    int kpairs = SEQ * NKV * (HD / 2);
    rope_kernel<<<(qpairs + 255) / 256, 256>>>(Qp, fc, fs, NH);
    rope_kernel<<<(kpairs + 255) / 256, 256>>>(Kp, fc, fs, NKV);

    // Attention (causal, GQA)
    attn_kernel<<<dim3(SEQ / BQ, NH), 256, attn_smem>>>(Qp, Kp, Vp, Op);

    // Output projection
    sgemm_nt<<<dim3(DIM / 128, SEQ / 128), 256>>>(Op, wo, out, SEQ, DIM, DIM);
}

// round 2
// speedup vs baseline: 1.5698x; 1.5698x over previous
#include <cuda_runtime.h>
#include <cuda_bf16.h>
#include <stdint.h>

#define SEQ    2048
#define DIM    4096
#define NH     32
#define NKV    8
#define HD     128
#define KV_DIM 1024   // NKV * HD
#define BQ     64
#define BK     64

// ---------------------------------------------------------------------------
// Static device scratch (no runtime allocation allowed)
// ---------------------------------------------------------------------------
__device__ float g_Q[SEQ * DIM];
__device__ float g_K[SEQ * KV_DIM];
__device__ float g_V[SEQ * KV_DIM];
__device__ float g_O[SEQ * DIM];

__device__ __nv_bfloat16 g_xh[SEQ * DIM],    g_xl[SEQ * DIM];
__device__ __nv_bfloat16 g_wqh[DIM * DIM],   g_wql[DIM * DIM];
__device__ __nv_bfloat16 g_wkh[KV_DIM * DIM], g_wkl[KV_DIM * DIM];
__device__ __nv_bfloat16 g_wvh[KV_DIM * DIM], g_wvl[KV_DIM * DIM];
__device__ __nv_bfloat16 g_woh[DIM * DIM],   g_wol[DIM * DIM];
__device__ __nv_bfloat16 g_oh[SEQ * DIM],    g_ol[SEQ * DIM];

// ---------------------------------------------------------------------------
// fp32 -> bf16 hi/lo split (vectorized by 4)
// ---------------------------------------------------------------------------
__global__ void split_bf16(const float* __restrict__ in,
                           __nv_bfloat16* __restrict__ hi,
                           __nv_bfloat16* __restrict__ lo, int n4) {
    int i = blockIdx.x * blockDim.x + threadIdx.x;
    if (i >= n4) return;
    float4 v = ((const float4*)in)[i];
    __nv_bfloat16 h0 = __float2bfloat16(v.x);
    __nv_bfloat16 h1 = __float2bfloat16(v.y);
    __nv_bfloat16 h2 = __float2bfloat16(v.z);
    __nv_bfloat16 h3 = __float2bfloat16(v.w);
    __nv_bfloat16 l0 = __float2bfloat16(v.x - __bfloat162float(h0));
    __nv_bfloat16 l1 = __float2bfloat16(v.y - __bfloat162float(h1));
    __nv_bfloat16 l2 = __float2bfloat16(v.z - __bfloat162float(h2));
    __nv_bfloat16 l3 = __float2bfloat16(v.w - __bfloat162float(h3));
    __nv_bfloat162* hp = (__nv_bfloat162*)hi;
    __nv_bfloat162* lp = (__nv_bfloat162*)lo;
    hp[i * 2 + 0] = __halves2bfloat162(h0, h1);
    hp[i * 2 + 1] = __halves2bfloat162(h2, h3);
    lp[i * 2 + 0] = __halves2bfloat162(l0, l1);
    lp[i * 2 + 1] = __halves2bfloat162(l2, l3);
}

// ---------------------------------------------------------------------------
// Tensor-core GEMM (NT): C[M,N] = A[M,K] @ B[N,K]^T, fp32-accurate via
// 3-term bf16 split:  Ah*Bh + Ah*Bl + Al*Bh.
// 128x128 CTA tile, k-chunk 32, 256 threads (8 warps, 4m x 2n), warp 32x64.
// ---------------------------------------------------------------------------
__device__ __forceinline__ uint32_t smaddr(const void* p) {
    return (uint32_t)__cvta_generic_to_shared(p);
}

__device__ __forceinline__ void ldsm4(uint32_t& r0, uint32_t& r1,
                                      uint32_t& r2, uint32_t& r3, uint32_t a) {
    asm volatile("ldmatrix.sync.aligned.m8n8.x4.shared.b16 {%0,%1,%2,%3}, [%4];"
                 : "=r"(r0), "=r"(r1), "=r"(r2), "=r"(r3) : "r"(a));
}

__device__ __forceinline__ void mma16816(float* c, const uint32_t* a,
                                         uint32_t b0, uint32_t b1) {
    asm volatile(
        "mma.sync.aligned.m16n8k16.row.col.f32.bf16.bf16.f32 "
        "{%0,%1,%2,%3},{%4,%5,%6,%7},{%8,%9},{%0,%1,%2,%3};"
        : "+f"(c[0]), "+f"(c[1]), "+f"(c[2]), "+f"(c[3])
        : "r"(a[0]), "r"(a[1]), "r"(a[2]), "r"(a[3]), "r"(b0), "r"(b1));
}

__global__ __launch_bounds__(256)
void gemm_bf16x3(const __nv_bfloat16* __restrict__ Ah,
                 const __nv_bfloat16* __restrict__ Al,
                 const __nv_bfloat16* __restrict__ Bh,
                 const __nv_bfloat16* __restrict__ Bl,
                 float* __restrict__ C, int M, int N, int K) {
    __shared__ __nv_bfloat16 Ash[128][40];   // pad 8 halves -> conflict-free ldmatrix
    __shared__ __nv_bfloat16 Asl[128][40];
    __shared__ __nv_bfloat16 Bsh[128][40];
    __shared__ __nv_bfloat16 Bsl[128][40];

    const int tid  = threadIdx.x;
    const int lane = tid & 31;
    const int wid  = tid >> 5;
    const int m0 = blockIdx.y * 128;
    const int n0 = blockIdx.x * 128;
    const int wm = (wid >> 1) * 32;   // 0,32,64,96
    const int wn = (wid & 1) * 64;    // 0,64

    // global load mapping: 512 x 16B per tile; 2 per thread
    const int idx0 = tid * 2, idx1 = tid * 2 + 1;
    const int ar0 = idx0 >> 2, ac0 = (idx0 & 3) * 8;
    const int ar1 = idx1 >> 2, ac1 = (idx1 & 3) * 8;

    float acc[2][8][4];
#pragma unroll
    for (int i = 0; i < 2; ++i)
#pragma unroll
        for (int j = 0; j < 8; ++j)
#pragma unroll
            for (int q = 0; q < 4; ++q) acc[i][j][q] = 0.0f;

    uint4 pa_h[2], pa_l[2], pb_h[2], pb_l[2];

#define LOADG(T) do {                                                          \
    int kc = (T) * 32;                                                         \
    pa_h[0] = *(const uint4*)(Ah + (long)(m0 + ar0) * K + kc + ac0);           \
    pa_h[1] = *(const uint4*)(Ah + (long)(m0 + ar1) * K + kc + ac1);           \
    pa_l[0] = *(const uint4*)(Al + (long)(m0 + ar0) * K + kc + ac0);           \
    pa_l[1] = *(const uint4*)(Al + (long)(m0 + ar1) * K + kc + ac1);           \
    pb_h[0] = *(const uint4*)(Bh + (long)(n0 + ar0) * K + kc + ac0);           \
    pb_h[1] = *(const uint4*)(Bh + (long)(n0 + ar1) * K + kc + ac1);           \
    pb_l[0] = *(const uint4*)(Bl + (long)(n0 + ar0) * K + kc + ac0);           \
    pb_l[1] = *(const uint4*)(Bl + (long)(n0 + ar1) * K + kc + ac1);           \
} while (0)

    LOADG(0);

    const int nk = K >> 5;
    for (int t = 0; t < nk; ++t) {
        __syncthreads();
        *(uint4*)&Ash[ar0][ac0] = pa_h[0];  *(uint4*)&Ash[ar1][ac1] = pa_h[1];
        *(uint4*)&Asl[ar0][ac0] = pa_l[0];  *(uint4*)&Asl[ar1][ac1] = pa_l[1];
        *(uint4*)&Bsh[ar0][ac0] = pb_h[0];  *(uint4*)&Bsh[ar1][ac1] = pb_h[1];
        *(uint4*)&Bsl[ar0][ac0] = pb_l[0];  *(uint4*)&Bsl[ar1][ac1] = pb_l[1];
        __syncthreads();
        if (t + 1 < nk) LOADG(t + 1);   // prefetch overlaps compute below

#pragma unroll
        for (int kb = 0; kb < 32; kb += 16) {
            uint32_t ah[2][4], al[2][4];
#pragma unroll
            for (int mf = 0; mf < 2; ++mf) {
                int arow = wm + mf * 16 + (lane & 15);
                int acol = kb + ((lane >> 4) << 3);
                ldsm4(ah[mf][0], ah[mf][1], ah[mf][2], ah[mf][3],
                      smaddr(&Ash[arow][acol]));
                ldsm4(al[mf][0], al[mf][1], al[mf][2], al[mf][3],
                      smaddr(&Asl[arow][acol]));
            }
#pragma unroll
            for (int np = 0; np < 4; ++np) {
                int brow = wn + np * 16 + (lane & 7) + ((lane >> 4) << 3);
                int bcol = kb + (((lane >> 3) & 1) << 3);
                uint32_t bh[4], bl[4];
                ldsm4(bh[0], bh[1], bh[2], bh[3], smaddr(&Bsh[brow][bcol]));
                ldsm4(bl[0], bl[1], bl[2], bl[3], smaddr(&Bsl[brow][bcol]));
#pragma unroll
                for (int hfv = 0; hfv < 2; ++hfv) {
                    int nf = np * 2 + hfv;
                    uint32_t b0h = bh[hfv * 2], b1h = bh[hfv * 2 + 1];
                    uint32_t b0l = bl[hfv * 2], b1l = bl[hfv * 2 + 1];
#pragma unroll
                    for (int mf = 0; mf < 2; ++mf) {
                        mma16816(acc[mf][nf], ah[mf], b0h, b1h);  // Ah*Bh
                        mma16816(acc[mf][nf], ah[mf], b0l, b1l);  // Ah*Bl
                        mma16816(acc[mf][nf], al[mf], b0h, b1h);  // Al*Bh
                    }
                }
            }
        }
    }
#undef LOADG

    // Epilogue
#pragma unroll
    for (int mf = 0; mf < 2; ++mf) {
        int row = m0 + wm + mf * 16 + (lane >> 2);
#pragma unroll
        for (int nf = 0; nf < 8; ++nf) {
            int col = n0 + wn + nf * 8 + (lane & 3) * 2;
            float2 v0 = make_float2(acc[mf][nf][0], acc[mf][nf][1]);
            float2 v1 = make_float2(acc[mf][nf][2], acc[mf][nf][3]);
            *(float2*)&C[(long)row * N + col]       = v0;
            *(float2*)&C[(long)(row + 8) * N + col] = v1;
        }
    }
}

// ---------------------------------------------------------------------------
// RoPE (interleaved pairs), in place on [SEQ, nheads*HD]
// ---------------------------------------------------------------------------
__global__ void rope_kernel(float* __restrict__ X,
                            const float* __restrict__ cs,
                            const float* __restrict__ sn,
                            int nheads) {
    int pps = nheads * (HD / 2);
    int total = SEQ * pps;
    int idx = blockIdx.x * blockDim.x + threadIdx.x;
    if (idx >= total) return;
    int s = idx / pps;
    int r = idx - s * pps;
    int p = r & 63;
    float2 v = ((float2*)X)[(long)s * pps + r];
    float c  = cs[s * 64 + p];
    float si = sn[s * 64 + p];
    float2 o;
    o.x = v.x * c - v.y * si;
    o.y = v.x * si + v.y * c;
    ((float2*)X)[(long)s * pps + r] = o;
}

// ---------------------------------------------------------------------------
// Flash attention (fp32, causal, GQA 4:1). One block = (head, 64-query tile).
// ---------------------------------------------------------------------------
#define ATTN_SMEM_FLOATS (128 * 64 + 128 * 64 + 64 * 128 + 64 * 64 + 3 * 64)

__global__ __launch_bounds__(256, 1)
void attn_kernel(const float* __restrict__ Q, const float* __restrict__ Kb,
                 const float* __restrict__ Vb, float* __restrict__ O) {
    extern __shared__ float smf[];
    float* Qs  = smf;                 // [128][64]  (d-major)
    float* Ks  = Qs + 128 * 64;       // [128][64]  (d-major)
    float* Vs  = Ks + 128 * 64;       // [64][128]
    float* St  = Vs + 64 * 128;       // [64][64]   St[j][i]
    float* mrow = St + 64 * 64;
    float* lrow = mrow + 64;
    float* arow = lrow + 64;

    int tid = threadIdx.x;
    int h   = blockIdx.y;
    int q0  = blockIdx.x * BQ;
    int kvh = h >> 2;
    const float scale = 0.08838834764831845f;
    const float NEG_INF = __int_as_float(0xff800000);

    for (int r = tid; r < BQ * (HD / 4); r += 256) {
        int i = r >> 5;
        int c = r & 31;
        float4 v = *(const float4*)&Q[(long)(q0 + i) * DIM + h * HD + c * 4];
        Qs[(c * 4 + 0) * 64 + i] = v.x;
        Qs[(c * 4 + 1) * 64 + i] = v.y;
        Qs[(c * 4 + 2) * 64 + i] = v.z;
        Qs[(c * 4 + 3) * 64 + i] = v.w;
    }
    if (tid < 64) { mrow[tid] = NEG_INF; lrow[tid] = 0.0f; }

    int tx = tid & 15;
    int ty = tid >> 4;

    float o[4][8];
#pragma unroll
    for (int i = 0; i < 4; ++i)
#pragma unroll
        for (int j = 0; j < 8; ++j) o[i][j] = 0.0f;

    int ntile = blockIdx.x + 1;
    for (int t = 0; t < ntile; ++t) {
        int j0 = t * BK;
        __syncthreads();

        for (int r = tid; r < BK * (HD / 4); r += 256) {
            int j = r >> 5;
            int c = r & 31;
            long gk = (long)(j0 + j) * KV_DIM + kvh * HD + c * 4;
            float4 kv = *(const float4*)&Kb[gk];
            Ks[(c * 4 + 0) * 64 + j] = kv.x;
            Ks[(c * 4 + 1) * 64 + j] = kv.y;
            Ks[(c * 4 + 2) * 64 + j] = kv.z;
            Ks[(c * 4 + 3) * 64 + j] = kv.w;
            float4 vv = *(const float4*)&Vb[gk];
            *(float4*)&Vs[j * 128 + c * 4] = vv;
        }
        __syncthreads();

        float s[4][4];
#pragma unroll
        for (int i = 0; i < 4; ++i)
#pragma unroll
            for (int j = 0; j < 4; ++j) s[i][j] = 0.0f;

#pragma unroll 4
        for (int d = 0; d < HD; ++d) {
            float4 qf = *(const float4*)(Qs + d * 64 + (ty << 2));
            float4 kf = *(const float4*)(Ks + d * 64 + (tx << 2));
            float qa[4] = {qf.x, qf.y, qf.z, qf.w};
            float ka[4] = {kf.x, kf.y, kf.z, kf.w};
#pragma unroll
            for (int ii = 0; ii < 4; ++ii)
#pragma unroll
                for (int jj = 0; jj < 4; ++jj) s[ii][jj] += qa[ii] * ka[jj];
        }

        bool diag = (j0 == q0);
#pragma unroll
        for (int ii = 0; ii < 4; ++ii) {
            int i = ty * 4 + ii;
#pragma unroll
            for (int jj = 0; jj < 4; ++jj) {
                int j = tx * 4 + jj;
                float val = s[ii][jj] * scale;
                if (diag && j > i) val = -1e30f;
                St[j * 64 + i] = val;
            }
        }
        __syncthreads();

        if (tid < 64) {
            int i = tid;
            float mold = mrow[i];
            float mt = NEG_INF;
            for (int j = 0; j < BK; ++j) mt = fmaxf(mt, St[j * 64 + i]);
            float mn = fmaxf(mold, mt);
            float alpha = __expf(mold - mn);
            float sum = 0.0f;
            for (int j = 0; j < BK; ++j) {
                float p = __expf(St[j * 64 + i] - mn);
                St[j * 64 + i] = p;
                sum += p;
            }
            lrow[i] = lrow[i] * alpha + sum;
            mrow[i] = mn;
            arow[i] = alpha;
        }
        __syncthreads();

        float al[4];
#pragma unroll
        for (int ii = 0; ii < 4; ++ii) al[ii] = arow[ty * 4 + ii];
#pragma unroll
        for (int ii = 0; ii < 4; ++ii)
#pragma unroll
            for (int jj = 0; jj < 8; ++jj) o[ii][jj] *= al[ii];

#pragma unroll 2
        for (int j = 0; j < BK; ++j) {
            float4 pf = *(const float4*)(St + j * 64 + (ty << 2));
            float4 v0 = *(const float4*)(Vs + j * 128 + (tx << 3));
            float4 v1 = *(const float4*)(Vs + j * 128 + (tx << 3) + 4);
            float pa[4] = {pf.x, pf.y, pf.z, pf.w};
            float va[8] = {v0.x, v0.y, v0.z, v0.w, v1.x, v1.y, v1.z, v1.w};
#pragma unroll
            for (int ii = 0; ii < 4; ++ii)
#pragma unroll
                for (int jj = 0; jj < 8; ++jj) o[ii][jj] += pa[ii] * va[jj];
        }
    }

#pragma unroll
    for (int ii = 0; ii < 4; ++ii) {
        int i = ty * 4 + ii;
        float inv = 1.0f / lrow[i];
        float4 w0 = make_float4(o[ii][0] * inv, o[ii][1] * inv,
                                o[ii][2] * inv, o[ii][3] * inv);
        float4 w1 = make_float4(o[ii][4] * inv, o[ii][5] * inv,
                                o[ii][6] * inv, o[ii][7] * inv);
        long base = (long)(q0 + i) * DIM + h * HD + (tx << 3);
        *(float4*)&O[base]     = w0;
        *(float4*)&O[base + 4] = w1;
    }
}

// ---------------------------------------------------------------------------
// Launcher
// ---------------------------------------------------------------------------
extern "C" void kernel_launch(void* const* d_in, const int* in_sizes, int n_in,
                              void* d_out, int out_size) {
    const float* x  = (const float*)d_in[0];
    const float* wq = (const float*)d_in[1];
    const float* wk = (const float*)d_in[2];
    const float* wv = (const float*)d_in[3];
    const float* wo = (const float*)d_in[4];
    const float* fc = (const float*)d_in[5];
    const float* fs = (const float*)d_in[6];
    float* out = (float*)d_out;

    float *Qp, *Kp, *Vp, *Op;
    cudaGetSymbolAddress((void**)&Qp, g_Q);
    cudaGetSymbolAddress((void**)&Kp, g_K);
    cudaGetSymbolAddress((void**)&Vp, g_V);
    cudaGetSymbolAddress((void**)&Op, g_O);

    __nv_bfloat16 *xh, *xl, *wqh, *wql, *wkh, *wkl, *wvh, *wvl, *woh, *wol, *oh, *ol;
    cudaGetSymbolAddress((void**)&xh,  g_xh);  cudaGetSymbolAddress((void**)&xl,  g_xl);
    cudaGetSymbolAddress((void**)&wqh, g_wqh); cudaGetSymbolAddress((void**)&wql, g_wql);
    cudaGetSymbolAddress((void**)&wkh, g_wkh); cudaGetSymbolAddress((void**)&wkl, g_wkl);
    cudaGetSymbolAddress((void**)&wvh, g_wvh); cudaGetSymbolAddress((void**)&wvl, g_wvl);
    cudaGetSymbolAddress((void**)&woh, g_woh); cudaGetSymbolAddress((void**)&wol, g_wol);
    cudaGetSymbolAddress((void**)&oh,  g_oh);  cudaGetSymbolAddress((void**)&ol,  g_ol);

    const int attn_smem = ATTN_SMEM_FLOATS * (int)sizeof(float);
    cudaFuncSetAttribute(attn_kernel,
                         cudaFuncAttributeMaxDynamicSharedMemorySize, attn_smem);

    // hi/lo splits
    auto launch_split = [](const float* in, __nv_bfloat16* hi, __nv_bfloat16* lo, int n) {
        int n4 = n / 4;
        split_bf16<<<(n4 + 255) / 256, 256>>>(in, hi, lo, n4);
    };
    launch_split(x,  xh,  xl,  SEQ * DIM);
    launch_split(wq, wqh, wql, DIM * DIM);
    launch_split(wk, wkh, wkl, KV_DIM * DIM);
    launch_split(wv, wvh, wvl, KV_DIM * DIM);
    launch_split(wo, woh, wol, DIM * DIM);

    // Projections (tensor cores)
    gemm_bf16x3<<<dim3(DIM / 128, SEQ / 128), 256>>>(xh, xl, wqh, wql, Qp, SEQ, DIM, DIM);
    gemm_bf16x3<<<dim3(KV_DIM / 128, SEQ / 128), 256>>>(xh, xl, wkh, wkl, Kp, SEQ, KV_DIM, DIM);
    gemm_bf16x3<<<dim3(KV_DIM / 128, SEQ / 128), 256>>>(xh, xl, wvh, wvl, Vp, SEQ, KV_DIM, DIM);

    // RoPE on Q and K
    int qpairs = SEQ * NH * (HD / 2);
    int kpairs = SEQ * NKV * (HD / 2);
    rope_kernel<<<(qpairs + 255) / 256, 256>>>(Qp, fc, fs, NH);
    rope_kernel<<<(kpairs + 255) / 256, 256>>>(Kp, fc, fs, NKV);

    // Attention (causal, GQA)
    attn_kernel<<<dim3(SEQ / BQ, NH), 256, attn_smem>>>(Qp, Kp, Vp, Op);

    // Output projection (tensor cores)
    launch_split(Op, oh, ol, SEQ * DIM);
    gemm_bf16x3<<<dim3(DIM / 128, SEQ / 128), 256>>>(oh, ol, woh, wol, out, SEQ, DIM, DIM);
}

// round 3
// speedup vs baseline: 2.6890x; 1.7130x over previous
#include <cuda_runtime.h>
#include <cuda_bf16.h>
#include <stdint.h>

#define SEQ    2048
#define DIM    4096
#define NH     32
#define NKV    8
#define HD     128
#define KV_DIM 1024
#define BQT    128      // attention query tile
#define BKT    64       // attention kv tile
#define PADK   136      // padded row (halves): 272B, 272%128==16 -> ldmatrix conflict-free

// ---------------------------------------------------------------------------
// Static device scratch
// ---------------------------------------------------------------------------
__device__ float g_Q[SEQ * DIM];
__device__ float g_K[SEQ * KV_DIM];
__device__ float g_V[SEQ * KV_DIM];
__device__ float g_O[SEQ * DIM];

__device__ __nv_bfloat16 g_xh[SEQ * DIM],     g_xl[SEQ * DIM];
__device__ __nv_bfloat16 g_wqh[DIM * DIM],    g_wql[DIM * DIM];
__device__ __nv_bfloat16 g_wkh[KV_DIM * DIM], g_wkl[KV_DIM * DIM];
__device__ __nv_bfloat16 g_wvh[KV_DIM * DIM], g_wvl[KV_DIM * DIM];
__device__ __nv_bfloat16 g_woh[DIM * DIM],    g_wol[DIM * DIM];
__device__ __nv_bfloat16 g_oh[SEQ * DIM],     g_ol[SEQ * DIM];

__device__ __nv_bfloat16 g_Qh[SEQ * DIM],     g_Ql[SEQ * DIM];
__device__ __nv_bfloat16 g_Kh[SEQ * KV_DIM],  g_Kl[SEQ * KV_DIM];
__device__ __nv_bfloat16 g_Vh[SEQ * KV_DIM],  g_Vl[SEQ * KV_DIM];

// ---------------------------------------------------------------------------
// Helpers
// ---------------------------------------------------------------------------
__device__ __forceinline__ uint32_t smaddr(const void* p) {
    return (uint32_t)__cvta_generic_to_shared(p);
}
__device__ __forceinline__ void cp16(uint32_t s, const void* g) {
    asm volatile("cp.async.cg.shared.global [%0], [%1], 16;" :: "r"(s), "l"(g));
}
__device__ __forceinline__ void cp_commit() {
    asm volatile("cp.async.commit_group;");
}
__device__ __forceinline__ void ldsm4(uint32_t& r0, uint32_t& r1,
                                      uint32_t& r2, uint32_t& r3, uint32_t a) {
    asm volatile("ldmatrix.sync.aligned.m8n8.x4.shared.b16 {%0,%1,%2,%3}, [%4];"
                 : "=r"(r0), "=r"(r1), "=r"(r2), "=r"(r3) : "r"(a));
}
__device__ __forceinline__ void ldsm4t(uint32_t& r0, uint32_t& r1,
                                       uint32_t& r2, uint32_t& r3, uint32_t a) {
    asm volatile("ldmatrix.sync.aligned.m8n8.x4.trans.shared.b16 {%0,%1,%2,%3}, [%4];"
                 : "=r"(r0), "=r"(r1), "=r"(r2), "=r"(r3) : "r"(a));
}
__device__ __forceinline__ void mma16816(float* c, const uint32_t* a,
                                         uint32_t b0, uint32_t b1) {
    asm volatile(
        "mma.sync.aligned.m16n8k16.row.col.f32.bf16.bf16.f32 "
        "{%0,%1,%2,%3},{%4,%5,%6,%7},{%8,%9},{%0,%1,%2,%3};"
        : "+f"(c[0]), "+f"(c[1]), "+f"(c[2]), "+f"(c[3])
        : "r"(a[0]), "r"(a[1]), "r"(a[2]), "r"(a[3]), "r"(b0), "r"(b1));
}
__device__ __forceinline__ uint32_t bpack(float a, float b) {
    __nv_bfloat162 v;
    v.x = __float2bfloat16(a);
    v.y = __float2bfloat16(b);
    return *(uint32_t*)&v;
}

// ---------------------------------------------------------------------------
// fp32 -> bf16 hi/lo split
// ---------------------------------------------------------------------------
__global__ void split_bf16(const float* __restrict__ in,
                           __nv_bfloat16* __restrict__ hi,
                           __nv_bfloat16* __restrict__ lo, int n4) {
    int i = blockIdx.x * blockDim.x + threadIdx.x;
    if (i >= n4) return;
    float4 v = ((const float4*)in)[i];
    __nv_bfloat16 h0 = __float2bfloat16(v.x);
    __nv_bfloat16 h1 = __float2bfloat16(v.y);
    __nv_bfloat16 h2 = __float2bfloat16(v.z);
    __nv_bfloat16 h3 = __float2bfloat16(v.w);
    __nv_bfloat162* hp = (__nv_bfloat162*)hi;
    __nv_bfloat162* lp = (__nv_bfloat162*)lo;
    hp[i * 2 + 0] = __halves2bfloat162(h0, h1);
    hp[i * 2 + 1] = __halves2bfloat162(h2, h3);
    lp[i * 2 + 0] = __halves2bfloat162(
        __float2bfloat16(v.x - __bfloat162float(h0)),
        __float2bfloat16(v.y - __bfloat162float(h1)));
    lp[i * 2 + 1] = __halves2bfloat162(
        __float2bfloat16(v.z - __bfloat162float(h2)),
        __float2bfloat16(v.w - __bfloat162float(h3)));
}

// ---------------------------------------------------------------------------
// RoPE + optional score-scale + bf16 hi/lo split (one pair per thread)
// ---------------------------------------------------------------------------
__global__ void rope_split(const float* __restrict__ X,
                           __nv_bfloat16* __restrict__ Xh,
                           __nv_bfloat16* __restrict__ Xl,
                           const float* __restrict__ cs,
                           const float* __restrict__ sn,
                           int nheads, float scale) {
    int pps = nheads * (HD / 2);
    int total = SEQ * pps;
    int idx = blockIdx.x * blockDim.x + threadIdx.x;
    if (idx >= total) return;
    int s = idx / pps;
    int r = idx - s * pps;
    int p = r & 63;
    float2 v = ((const float2*)X)[idx];
    float c = cs[s * 64 + p], si = sn[s * 64 + p];
    float o0 = (v.x * c - v.y * si) * scale;
    float o1 = (v.x * si + v.y * c) * scale;
    __nv_bfloat16 h0 = __float2bfloat16(o0);
    __nv_bfloat16 h1 = __float2bfloat16(o1);
    ((__nv_bfloat162*)Xh)[idx] = __halves2bfloat162(h0, h1);
    ((__nv_bfloat162*)Xl)[idx] = __halves2bfloat162(
        __float2bfloat16(o0 - __bfloat162float(h0)),
        __float2bfloat16(o1 - __bfloat162float(h1)));
}

// ---------------------------------------------------------------------------
// Tensor-core GEMM (NT) with cp.async 2-stage pipeline.
// C[M,N] = A@B^T via 3-term bf16 split. 128x128 tile, k-chunk 32, 256 thr.
// ---------------------------------------------------------------------------
#define GEMM_T (128 * 40)
#define GEMM_SMEM (8 * GEMM_T * 2)

__global__ __launch_bounds__(256, 2)
void gemm_bf16x3(const __nv_bfloat16* __restrict__ Ah,
                 const __nv_bfloat16* __restrict__ Al,
                 const __nv_bfloat16* __restrict__ Bh,
                 const __nv_bfloat16* __restrict__ Bl,
                 float* __restrict__ C, int M, int N, int K) {
    extern __shared__ __nv_bfloat16 smg[];
    __nv_bfloat16* Ash[2] = {smg + 0 * GEMM_T, smg + 1 * GEMM_T};
    __nv_bfloat16* Asl[2] = {smg + 2 * GEMM_T, smg + 3 * GEMM_T};
    __nv_bfloat16* Bsh[2] = {smg + 4 * GEMM_T, smg + 5 * GEMM_T};
    __nv_bfloat16* Bsl[2] = {smg + 6 * GEMM_T, smg + 7 * GEMM_T};

    const int tid  = threadIdx.x;
    const int lane = tid & 31;
    const int wid  = tid >> 5;
    const int m0 = blockIdx.y * 128;
    const int n0 = blockIdx.x * 128;
    const int wm = (wid >> 1) * 32;
    const int wn = (wid & 1) * 64;

    const int idx0 = tid * 2, idx1 = tid * 2 + 1;
    const int ar0 = idx0 >> 2, ac0 = (idx0 & 3) * 8;
    const int ar1 = idx1 >> 2, ac1 = (idx1 & 3) * 8;

    float acc[2][8][4];
#pragma unroll
    for (int i = 0; i < 2; ++i)
#pragma unroll
        for (int j = 0; j < 8; ++j)
#pragma unroll
            for (int q = 0; q < 4; ++q) acc[i][j][q] = 0.0f;

#define ISSUE(T) do {                                                         \
    int kc = (T) * 32; int bb = (T) & 1;                                      \
    cp16(smaddr(Ash[bb] + ar0 * 40 + ac0), Ah + (long)(m0 + ar0) * K + kc + ac0); \
    cp16(smaddr(Ash[bb] + ar1 * 40 + ac1), Ah + (long)(m0 + ar1) * K + kc + ac1); \
    cp16(smaddr(Asl[bb] + ar0 * 40 + ac0), Al + (long)(m0 + ar0) * K + kc + ac0); \
    cp16(smaddr(Asl[bb] + ar1 * 40 + ac1), Al + (long)(m0 + ar1) * K + kc + ac1); \
    cp16(smaddr(Bsh[bb] + ar0 * 40 + ac0), Bh + (long)(n0 + ar0) * K + kc + ac0); \
    cp16(smaddr(Bsh[bb] + ar1 * 40 + ac1), Bh + (long)(n0 + ar1) * K + kc + ac1); \
    cp16(smaddr(Bsl[bb] + ar0 * 40 + ac0), Bl + (long)(n0 + ar0) * K + kc + ac0); \
    cp16(smaddr(Bsl[bb] + ar1 * 40 + ac1), Bl + (long)(n0 + ar1) * K + kc + ac1); \
    cp_commit();                                                              \
} while (0)

    ISSUE(0);

    const int nk = K >> 5;
    for (int t = 0; t < nk; ++t) {
        if (t + 1 < nk) {
            ISSUE(t + 1);
            asm volatile("cp.async.wait_group 1;");
        } else {
            asm volatile("cp.async.wait_group 0;");
        }
        __syncthreads();
        const int buf = t & 1;
        const __nv_bfloat16* pAh = Ash[buf];
        const __nv_bfloat16* pAl = Asl[buf];
        const __nv_bfloat16* pBh = Bsh[buf];
        const __nv_bfloat16* pBl = Bsl[buf];

#pragma unroll
        for (int kb = 0; kb < 32; kb += 16) {
            uint32_t ah[2][4], al[2][4];
#pragma unroll
            for (int mf = 0; mf < 2; ++mf) {
                int arow = wm + mf * 16 + (lane & 15);
                int acol = kb + ((lane >> 4) << 3);
                ldsm4(ah[mf][0], ah[mf][1], ah[mf][2], ah[mf][3],
                      smaddr(pAh + arow * 40 + acol));
                ldsm4(al[mf][0], al[mf][1], al[mf][2], al[mf][3],
                      smaddr(pAl + arow * 40 + acol));
            }
#pragma unroll
            for (int np = 0; np < 4; ++np) {
                int brow = wn + np * 16 + (lane & 7) + ((lane >> 4) << 3);
                int bcol = kb + (((lane >> 3) & 1) << 3);
                uint32_t bh[4], bl[4];
                ldsm4(bh[0], bh[1], bh[2], bh[3], smaddr(pBh + brow * 40 + bcol));
                ldsm4(bl[0], bl[1], bl[2], bl[3], smaddr(pBl + brow * 40 + bcol));
#pragma unroll
                for (int hfv = 0; hfv < 2; ++hfv) {
                    int nf = np * 2 + hfv;
#pragma unroll
                    for (int mf = 0; mf < 2; ++mf) {
                        mma16816(acc[mf][nf], ah[mf], bh[hfv * 2], bh[hfv * 2 + 1]);
                        mma16816(acc[mf][nf], ah[mf], bl[hfv * 2], bl[hfv * 2 + 1]);
                        mma16816(acc[mf][nf], al[mf], bh[hfv * 2], bh[hfv * 2 + 1]);
                    }
                }
            }
        }
        __syncthreads();
    }
#undef ISSUE

#pragma unroll
    for (int mf = 0; mf < 2; ++mf) {
        int row = m0 + wm + mf * 16 + (lane >> 2);
#pragma unroll
        for (int nf = 0; nf < 8; ++nf) {
            int col = n0 + wn + nf * 8 + (lane & 3) * 2;
            *(float2*)&C[(long)row * N + col] =
                make_float2(acc[mf][nf][0], acc[mf][nf][1]);
            *(float2*)&C[(long)(row + 8) * N + col] =
                make_float2(acc[mf][nf][2], acc[mf][nf][3]);
        }
    }
}

// ---------------------------------------------------------------------------
// Tensor-core flash attention (causal, GQA 4:1), 3-term bf16 split everywhere.
// CTA = (head, 128-query tile), 256 threads = 8 warps (16 rows each).
// S lives in register C-fragments; P->A-fragment repack is register-only.
// K/V hi/lo staged in smem via cp.async double buffer.
// ---------------------------------------------------------------------------
#define ATT_TS (64 * PADK)                 // halves per stage-array
#define ATT_SMEM (8 * ATT_TS * 2)          // bytes

__device__ __forceinline__ void attn_issue(
    const __nv_bfloat16* Kh_, const __nv_bfloat16* Kl_,
    const __nv_bfloat16* Vh_, const __nv_bfloat16* Vl_,
    __nv_bfloat16* sKh, __nv_bfloat16* sKl,
    __nv_bfloat16* sVh, __nv_bfloat16* sVl,
    int j0, int kvh, int tid) {
#pragma unroll
    for (int i = 0; i < 4; ++i) {
        int c = tid + 256 * i;
        int row = c >> 4, c16 = c & 15;
        long g = (long)(j0 + row) * KV_DIM + kvh * HD + c16 * 8;
        int so = row * PADK + c16 * 8;
        cp16(smaddr(sKh + so), Kh_ + g);
        cp16(smaddr(sKl + so), Kl_ + g);
        cp16(smaddr(sVh + so), Vh_ + g);
        cp16(smaddr(sVl + so), Vl_ + g);
    }
    cp_commit();
}

__global__ __launch_bounds__(256, 1)
void attn_mma(const __nv_bfloat16* __restrict__ Qh,
              const __nv_bfloat16* __restrict__ Ql,
              const __nv_bfloat16* __restrict__ Kh_,
              const __nv_bfloat16* __restrict__ Kl_,
              const __nv_bfloat16* __restrict__ Vh_,
              const __nv_bfloat16* __restrict__ Vl_,
              float* __restrict__ O) {
    extern __shared__ __nv_bfloat16 sma[];
    __nv_bfloat16* sKh[2] = {sma + 0 * ATT_TS, sma + 1 * ATT_TS};
    __nv_bfloat16* sKl[2] = {sma + 2 * ATT_TS, sma + 3 * ATT_TS};
    __nv_bfloat16* sVh[2] = {sma + 4 * ATT_TS, sma + 5 * ATT_TS};
    __nv_bfloat16* sVl[2] = {sma + 6 * ATT_TS, sma + 7 * ATT_TS};

    const int tid = threadIdx.x;
    const int lane = tid & 31;
    const int w = tid >> 5;
    const int g = lane >> 2;
    const int qq = lane & 3;
    const int h = blockIdx.y;
    const int kvh = h >> 2;
    const int qt = gridDim.x - 1 - blockIdx.x;   // big tiles scheduled first
    const int q0 = qt * BQT;

    // Q A-fragments (hi/lo) loaded straight from global, held in registers
    const int r0 = q0 + w * 16 + g;
    const int r1 = r0 + 8;
    uint32_t qfh[8][4], qfl[8][4];
#pragma unroll
    for (int k = 0; k < 8; ++k) {
        int c = h * HD + k * 16 + qq * 2;
        qfh[k][0] = *(const uint32_t*)&Qh[(long)r0 * DIM + c];
        qfh[k][1] = *(const uint32_t*)&Qh[(long)r1 * DIM + c];
        qfh[k][2] = *(const uint32_t*)&Qh[(long)r0 * DIM + c + 8];
        qfh[k][3] = *(const uint32_t*)&Qh[(long)r1 * DIM + c + 8];
        qfl[k][0] = *(const uint32_t*)&Ql[(long)r0 * DIM + c];
        qfl[k][1] = *(const uint32_t*)&Ql[(long)r1 * DIM + c];
        qfl[k][2] = *(const uint32_t*)&Ql[(long)r0 * DIM + c + 8];
        qfl[k][3] = *(const uint32_t*)&Ql[(long)r1 * DIM + c + 8];
    }

    float of[16][4];
#pragma unroll
    for (int i = 0; i < 16; ++i)
#pragma unroll
        for (int j = 0; j < 4; ++j) of[i][j] = 0.0f;
    float m0 = -1e30f, m1 = -1e30f, l0 = 0.0f, l1 = 0.0f;

    const int nt = 2 * qt + 2;
    attn_issue(Kh_, Kl_, Vh_, Vl_, sKh[0], sKl[0], sVh[0], sVl[0], 0, kvh, tid);

    for (int t = 0; t < nt; ++t) {
        if (t + 1 < nt) {
            int bb = (t + 1) & 1;
            attn_issue(Kh_, Kl_, Vh_, Vl_, sKh[bb], sKl[bb], sVh[bb], sVl[bb],
                       (t + 1) * BKT, kvh, tid);
            asm volatile("cp.async.wait_group 1;");
        } else {
            asm volatile("cp.async.wait_group 0;");
        }
        __syncthreads();
        const int buf = t & 1;
        const int j0 = t * BKT;

        // ---- S = Q @ K^T (3-term) ----
        float sc[8][4];
#pragma unroll
        for (int i = 0; i < 8; ++i)
#pragma unroll
            for (int j = 0; j < 4; ++j) sc[i][j] = 0.0f;

#pragma unroll
        for (int k = 0; k < 8; ++k) {
#pragma unroll
            for (int np = 0; np < 4; ++np) {
                int brow = np * 16 + (lane & 7) + ((lane >> 4) << 3);
                int bcol = k * 16 + (((lane >> 3) & 1) << 3);
                uint32_t bh[4], bl[4];
                ldsm4(bh[0], bh[1], bh[2], bh[3],
                      smaddr(sKh[buf] + brow * PADK + bcol));
                ldsm4(bl[0], bl[1], bl[2], bl[3],
                      smaddr(sKl[buf] + brow * PADK + bcol));
#pragma unroll
                for (int hf = 0; hf < 2; ++hf) {
                    int nf = np * 2 + hf;
                    mma16816(sc[nf], qfh[k], bh[hf * 2], bh[hf * 2 + 1]);
                    mma16816(sc[nf], qfh[k], bl[hf * 2], bl[hf * 2 + 1]);
                    mma16816(sc[nf], qfl[k], bh[hf * 2], bh[hf * 2 + 1]);
                }
            }
        }

        // ---- causal mask (only last two tiles cross the diagonal) ----
        if (t >= nt - 2) {
#pragma unroll
            for (int nf = 0; nf < 8; ++nf) {
                int cb = j0 + nf * 8 + qq * 2;
                if (cb > r0)     sc[nf][0] = -1e30f;
                if (cb + 1 > r0) sc[nf][1] = -1e30f;
                if (cb > r1)     sc[nf][2] = -1e30f;
                if (cb + 1 > r1) sc[nf][3] = -1e30f;
            }
        }

        // ---- online softmax (rows r0, r1 per thread; quad-redundant) ----
        float mt0 = -1e30f, mt1 = -1e30f;
#pragma unroll
        for (int nf = 0; nf < 8; ++nf) {
            mt0 = fmaxf(mt0, fmaxf(sc[nf][0], sc[nf][1]));
            mt1 = fmaxf(mt1, fmaxf(sc[nf][2], sc[nf][3]));
        }
        mt0 = fmaxf(mt0, __shfl_xor_sync(0xffffffff, mt0, 1));
        mt0 = fmaxf(mt0, __shfl_xor_sync(0xffffffff, mt0, 2));
        mt1 = fmaxf(mt1, __shfl_xor_sync(0xffffffff, mt1, 1));
        mt1 = fmaxf(mt1, __shfl_xor_sync(0xffffffff, mt1, 2));
        float mn0 = fmaxf(m0, mt0), mn1 = fmaxf(m1, mt1);
        float a0 = __expf(m0 - mn0), a1 = __expf(m1 - mn1);
        m0 = mn0; m1 = mn1;

        float rs0 = 0.0f, rs1 = 0.0f;
#pragma unroll
        for (int nf = 0; nf < 8; ++nf) {
            sc[nf][0] = __expf(sc[nf][0] - mn0); rs0 += sc[nf][0];
            sc[nf][1] = __expf(sc[nf][1] - mn0); rs0 += sc[nf][1];
            sc[nf][2] = __expf(sc[nf][2] - mn1); rs1 += sc[nf][2];
            sc[nf][3] = __expf(sc[nf][3] - mn1); rs1 += sc[nf][3];
        }
        rs0 += __shfl_xor_sync(0xffffffff, rs0, 1);
        rs0 += __shfl_xor_sync(0xffffffff, rs0, 2);
        rs1 += __shfl_xor_sync(0xffffffff, rs1, 1);
        rs1 += __shfl_xor_sync(0xffffffff, rs1, 2);
        l0 = l0 * a0 + rs0;
        l1 = l1 * a1 + rs1;

#pragma unroll
        for (int nf = 0; nf < 16; ++nf) {
            of[nf][0] *= a0; of[nf][1] *= a0;
            of[nf][2] *= a1; of[nf][3] *= a1;
        }

        // ---- O += P @ V (3-term); P repacked from S fragments ----
#pragma unroll
        for (int ks = 0; ks < 4; ++ks) {
            uint32_t ph[4], pl[4];
            {
                float s00 = sc[2 * ks][0],     s01 = sc[2 * ks][1];
                float s02 = sc[2 * ks][2],     s03 = sc[2 * ks][3];
                float s10 = sc[2 * ks + 1][0], s11 = sc[2 * ks + 1][1];
                float s12 = sc[2 * ks + 1][2], s13 = sc[2 * ks + 1][3];
                ph[0] = bpack(s00, s01); ph[1] = bpack(s02, s03);
                ph[2] = bpack(s10, s11); ph[3] = bpack(s12, s13);
                __nv_bfloat162* hp;
                hp = (__nv_bfloat162*)&ph[0];
                pl[0] = bpack(s00 - __bfloat162float(hp->x), s01 - __bfloat162float(hp->y));
                hp = (__nv_bfloat162*)&ph[1];
                pl[1] = bpack(s02 - __bfloat162float(hp->x), s03 - __bfloat162float(hp->y));
                hp = (__nv_bfloat162*)&ph[2];
                pl[2] = bpack(s10 - __bfloat162float(hp->x), s11 - __bfloat162float(hp->y));
                hp = (__nv_bfloat162*)&ph[3];
                pl[3] = bpack(s12 - __bfloat162float(hp->x), s13 - __bfloat162float(hp->y));
            }
            int vrow = ks * 16 + (lane & 7) + (((lane >> 3) & 1) << 3);
#pragma unroll
            for (int nn = 0; nn < 8; ++nn) {
                int vcol = nn * 16 + ((lane >> 4) << 3);
                uint32_t vh[4], vl[4];
                ldsm4t(vh[0], vh[1], vh[2], vh[3],
                       smaddr(sVh[buf] + vrow * PADK + vcol));
                ldsm4t(vl[0], vl[1], vl[2], vl[3],
                       smaddr(sVl[buf] + vrow * PADK + vcol));
                mma16816(of[nn * 2], ph, vh[0], vh[1]);
                mma16816(of[nn * 2], ph, vl[0], vl[1]);
                mma16816(of[nn * 2], pl, vh[0], vh[1]);
                mma16816(of[nn * 2 + 1], ph, vh[2], vh[3]);
                mma16816(of[nn * 2 + 1], ph, vl[2], vl[3]);
                mma16816(of[nn * 2 + 1], pl, vh[2], vh[3]);
            }
        }
        __syncthreads();
    }

    // ---- normalize + store ----
    float inv0 = 1.0f / l0, inv1 = 1.0f / l1;
#pragma unroll
    for (int nf = 0; nf < 16; ++nf) {
        int col = h * HD + nf * 8 + qq * 2;
        *(float2*)&O[(long)r0 * DIM + col] =
            make_float2(of[nf][0] * inv0, of[nf][1] * inv0);
        *(float2*)&O[(long)r1 * DIM + col] =
            make_float2(of[nf][2] * inv1, of[nf][3] * inv1);
    }
}

// ---------------------------------------------------------------------------
// Launcher
// ---------------------------------------------------------------------------
extern "C" void kernel_launch(void* const* d_in, const int* in_sizes, int n_in,
                              void* d_out, int out_size) {
    const float* x  = (const float*)d_in[0];
    const float* wq = (const float*)d_in[1];
    const float* wk = (const float*)d_in[2];
    const float* wv = (const float*)d_in[3];
    const float* wo = (const float*)d_in[4];
    const float* fc = (const float*)d_in[5];
    const float* fs = (const float*)d_in[6];
    float* out = (float*)d_out;

    float *Qp, *Kp, *Vp, *Op;
    cudaGetSymbolAddress((void**)&Qp, g_Q);
    cudaGetSymbolAddress((void**)&Kp, g_K);
    cudaGetSymbolAddress((void**)&Vp, g_V);
    cudaGetSymbolAddress((void**)&Op, g_O);

    __nv_bfloat16 *xh, *xl, *wqh, *wql, *wkh, *wkl, *wvh, *wvl, *woh, *wol, *oh, *ol;
    __nv_bfloat16 *qh, *ql, *kh, *kl, *vh, *vl;
    cudaGetSymbolAddress((void**)&xh,  g_xh);  cudaGetSymbolAddress((void**)&xl,  g_xl);
    cudaGetSymbolAddress((void**)&wqh, g_wqh); cudaGetSymbolAddress((void**)&wql, g_wql);
    cudaGetSymbolAddress((void**)&wkh, g_wkh); cudaGetSymbolAddress((void**)&wkl, g_wkl);
    cudaGetSymbolAddress((void**)&wvh, g_wvh); cudaGetSymbolAddress((void**)&wvl, g_wvl);
    cudaGetSymbolAddress((void**)&woh, g_woh); cudaGetSymbolAddress((void**)&wol, g_wol);
    cudaGetSymbolAddress((void**)&oh,  g_oh);  cudaGetSymbolAddress((void**)&ol,  g_ol);
    cudaGetSymbolAddress((void**)&qh,  g_Qh);  cudaGetSymbolAddress((void**)&ql,  g_Ql);
    cudaGetSymbolAddress((void**)&kh,  g_Kh);  cudaGetSymbolAddress((void**)&kl,  g_Kl);
    cudaGetSymbolAddress((void**)&vh,  g_Vh);  cudaGetSymbolAddress((void**)&vl,  g_Vl);

    cudaFuncSetAttribute(gemm_bf16x3,
                         cudaFuncAttributeMaxDynamicSharedMemorySize, GEMM_SMEM);
    cudaFuncSetAttribute(attn_mma,
                         cudaFuncAttributeMaxDynamicSharedMemorySize, ATT_SMEM);

    auto launch_split = [](const float* in, __nv_bfloat16* hi, __nv_bfloat16* lo, int n) {
        int n4 = n / 4;
        split_bf16<<<(n4 + 255) / 256, 256>>>(in, hi, lo, n4);
    };
    launch_split(x,  xh,  xl,  SEQ * DIM);
    launch_split(wq, wqh, wql, DIM * DIM);
    launch_split(wk, wkh, wkl, KV_DIM * DIM);
    launch_split(wv, wvh, wvl, KV_DIM * DIM);
    launch_split(wo, woh, wol, DIM * DIM);

    // Projections
    gemm_bf16x3<<<dim3(DIM / 128, SEQ / 128), 256, GEMM_SMEM>>>(xh, xl, wqh, wql, Qp, SEQ, DIM, DIM);
    gemm_bf16x3<<<dim3(KV_DIM / 128, SEQ / 128), 256, GEMM_SMEM>>>(xh, xl, wkh, wkl, Kp, SEQ, KV_DIM, DIM);
    gemm_bf16x3<<<dim3(KV_DIM / 128, SEQ / 128), 256, GEMM_SMEM>>>(xh, xl, wvh, wvl, Vp, SEQ, KV_DIM, DIM);

    // RoPE + split (Q pre-scaled by 1/sqrt(HD)); V split
    int qpairs = SEQ * NH * (HD / 2);
    int kpairs = SEQ * NKV * (HD / 2);
    rope_split<<<(qpairs + 255) / 256, 256>>>(Qp, qh, ql, fc, fs, NH, 0.08838834764831845f);
    rope_split<<<(kpairs + 255) / 256, 256>>>(Kp, kh, kl, fc, fs, NKV, 1.0f);
    launch_split(Vp, vh, vl, SEQ * KV_DIM);

    // Flash attention (tensor cores)
    attn_mma<<<dim3(SEQ / BQT, NH), 256, ATT_SMEM>>>(qh, ql, kh, kl, vh, vl, Op);

    // Output projection
    launch_split(Op, oh, ol, SEQ * DIM);
    gemm_bf16x3<<<dim3(DIM / 128, SEQ / 128), 256, GEMM_SMEM>>>(oh, ol, woh, wol, out, SEQ, DIM, DIM);
}

// round 5
// speedup vs baseline: 6.0494x; 2.2497x over previous
#include <cuda_runtime.h>
#include <cuda_bf16.h>
#include <stdint.h>

#define SEQ    2048
#define DIM    4096
#define NH     32
#define NKV    8
#define HD     128
#define KV_DIM 1024
#define BQT    128
#define BKT    64
#define PADK   136

#if defined(__CUDA_ARCH_FEAT_SM103_ALL) || defined(__CUDA_ARCH_FEAT_SM100_ALL)
#define HAS_TCGEN05 1
#else
#define HAS_TCGEN05 0
#endif

// ---------------------------------------------------------------------------
// Static device scratch
// ---------------------------------------------------------------------------
__device__ float g_Q[SEQ * DIM];
__device__ float g_K[SEQ * KV_DIM];
__device__ float g_V[SEQ * KV_DIM];
__device__ float g_O[SEQ * DIM];

__device__ __nv_bfloat16 g_xh[SEQ * DIM],     g_xl[SEQ * DIM];
__device__ __nv_bfloat16 g_wqh[DIM * DIM],    g_wql[DIM * DIM];
__device__ __nv_bfloat16 g_wkh[KV_DIM * DIM], g_wkl[KV_DIM * DIM];
__device__ __nv_bfloat16 g_wvh[KV_DIM * DIM], g_wvl[KV_DIM * DIM];
__device__ __nv_bfloat16 g_woh[DIM * DIM],    g_wol[DIM * DIM];
__device__ __nv_bfloat16 g_oh[SEQ * DIM],     g_ol[SEQ * DIM];

__device__ __nv_bfloat16 g_Qh[SEQ * DIM],     g_Ql[SEQ * DIM];
__device__ __nv_bfloat16 g_Kh[SEQ * KV_DIM],  g_Kl[SEQ * KV_DIM];
__device__ __nv_bfloat16 g_Vh[SEQ * KV_DIM],  g_Vl[SEQ * KV_DIM];

// ---------------------------------------------------------------------------
// Helpers
// ---------------------------------------------------------------------------
__device__ __forceinline__ uint32_t smaddr(const void* p) {
    return (uint32_t)__cvta_generic_to_shared(p);
}
__device__ __forceinline__ void cp16(uint32_t s, const void* g) {
    asm volatile("cp.async.cg.shared.global [%0], [%1], 16;" :: "r"(s), "l"(g));
}
__device__ __forceinline__ void cp_commit() {
    asm volatile("cp.async.commit_group;");
}
__device__ __forceinline__ void ldsm4(uint32_t& r0, uint32_t& r1,
                                      uint32_t& r2, uint32_t& r3, uint32_t a) {
    asm volatile("ldmatrix.sync.aligned.m8n8.x4.shared.b16 {%0,%1,%2,%3}, [%4];"
                 : "=r"(r0), "=r"(r1), "=r"(r2), "=r"(r3) : "r"(a));
}
__device__ __forceinline__ void ldsm4t(uint32_t& r0, uint32_t& r1,
                                       uint32_t& r2, uint32_t& r3, uint32_t a) {
    asm volatile("ldmatrix.sync.aligned.m8n8.x4.trans.shared.b16 {%0,%1,%2,%3}, [%4];"
                 : "=r"(r0), "=r"(r1), "=r"(r2), "=r"(r3) : "r"(a));
}
__device__ __forceinline__ void mma16816(float* c, const uint32_t* a,
                                         uint32_t b0, uint32_t b1) {
    asm volatile(
        "mma.sync.aligned.m16n8k16.row.col.f32.bf16.bf16.f32 "
        "{%0,%1,%2,%3},{%4,%5,%6,%7},{%8,%9},{%0,%1,%2,%3};"
        : "+f"(c[0]), "+f"(c[1]), "+f"(c[2]), "+f"(c[3])
        : "r"(a[0]), "r"(a[1]), "r"(a[2]), "r"(a[3]), "r"(b0), "r"(b1));
}
__device__ __forceinline__ uint32_t bpack(float a, float b) {
    __nv_bfloat162 v;
    v.x = __float2bfloat16(a);
    v.y = __float2bfloat16(b);
    return *(uint32_t*)&v;
}

// ---- tcgen05 (only referenced when HAS_TCGEN05) -----------------------------
static constexpr uint64_t SMEM_DESC_BASE_SW128 =
    (uint64_t(2)  << 61) | (uint64_t(1) << 46) |
    (uint64_t(64) << 32) | (uint64_t(1) << 16);
#define MAKE_SMEM_DESC(base_addr) \
    (SMEM_DESC_BASE_SW128 | ((uint64_t)((base_addr) >> 4) & 0x3FFF))

#define MBARRIER_INIT(mbar, count) \
    asm volatile("mbarrier.init.shared.b64 [%0], %1;" \
                 :: "r"((uint32_t)(mbar)), "r"((uint32_t)(count)) : "memory")
#define FENCE_ASYNC() \
    asm volatile("fence.proxy.async.shared::cta;" ::: "memory")

#define MBARRIER_WAIT_PARITY(mbar_smem_addr, phase_parity) do { \
    uint32_t _mbar = (uint32_t)(mbar_smem_addr); \
    uint32_t _parity = (uint32_t)(phase_parity); \
    uint32_t _done; \
    asm volatile( \
        "{\n\t.reg .pred p;\n\t" \
        "mbarrier.try_wait.parity.acquire.cta.shared::cta.b64 p, [%1], %2;\n\t" \
        "selp.b32 %0, 1, 0, p;\n\t}" \
        : "=r"(_done) : "r"(_mbar), "r"(_parity) : "memory"); \
    if (!_done) { \
        asm volatile( \
            "{\n\t.reg .pred P1;\n\t" \
            "WAIT_LOOP_%=:\n\t" \
            "mbarrier.try_wait.parity.acquire.cta.shared::cta.b64 P1, [%0], %1, 0x989680;\n\t" \
            "@P1 bra.uni WAIT_DONE_%=;\n\t" \
            "bra.uni WAIT_LOOP_%=;\n\t" \
            "WAIT_DONE_%=:\n\t}" \
            :: "r"(_mbar), "r"(_parity) : "memory"); \
    } \
} while(0)

#if HAS_TCGEN05
#define TCGEN05_ALLOC(smem_result_addr, nCols) \
    asm volatile("tcgen05.alloc.cta_group::1.sync.aligned.shared::cta.b32 [%0], %1;" \
                 :: "r"((uint32_t)(smem_result_addr)), "r"((uint32_t)(nCols)) : "memory")
#define TCGEN05_DEALLOC(tmem_addr, nCols) \
    asm volatile("tcgen05.dealloc.cta_group::1.sync.aligned.b32 %0, %1;" \
                 :: "r"(tmem_addr), "r"((uint32_t)(nCols)))
#define TCGEN05_RELINQ() \
    asm volatile("tcgen05.relinquish_alloc_permit.cta_group::1.sync.aligned;")
#define TCGEN05_COMMIT(mbar) \
    asm volatile("tcgen05.commit.cta_group::1.mbarrier::arrive::one.shared::cluster.b64 [%0];" \
                 :: "r"((uint32_t)(mbar)) : "memory")
#define TCGEN05_FENCE_AFTER() \
    asm volatile("tcgen05.fence::after_thread_sync;" ::: "memory")
#define TCGEN05_WAIT_LD() \
    asm volatile("tcgen05.wait::ld.sync.aligned;" ::: "memory")
#define TCGEN05_LD_X32(r, tmem_addr) \
    asm volatile( \
        "tcgen05.ld.sync.aligned.32x32b.x32.b32 " \
        "{%0, %1, %2, %3, %4, %5, %6, %7, " \
        " %8, %9, %10, %11, %12, %13, %14, %15, " \
        " %16, %17, %18, %19, %20, %21, %22, %23, " \
        " %24, %25, %26, %27, %28, %29, %30, %31}, [%32];" \
        : "=r"((r)[0]),  "=r"((r)[1]),  "=r"((r)[2]),  "=r"((r)[3]), \
          "=r"((r)[4]),  "=r"((r)[5]),  "=r"((r)[6]),  "=r"((r)[7]), \
          "=r"((r)[8]),  "=r"((r)[9]),  "=r"((r)[10]), "=r"((r)[11]), \
          "=r"((r)[12]), "=r"((r)[13]), "=r"((r)[14]), "=r"((r)[15]), \
          "=r"((r)[16]), "=r"((r)[17]), "=r"((r)[18]), "=r"((r)[19]), \
          "=r"((r)[20]), "=r"((r)[21]), "=r"((r)[22]), "=r"((r)[23]), \
          "=r"((r)[24]), "=r"((r)[25]), "=r"((r)[26]), "=r"((r)[27]), \
          "=r"((r)[28]), "=r"((r)[29]), "=r"((r)[30]), "=r"((r)[31]) \
        : "r"(tmem_addr))

__device__ __forceinline__ void umma_f16_ss(uint32_t d, uint64_t a, uint64_t b,
                                            uint32_t idesc, uint32_t en) {
    asm volatile(
        "{\n\t.reg .pred p;\n\t"
        "setp.ne.u32 p, %5, 0;\n\t"
        "tcgen05.mma.cta_group::1.kind::f16 [%0], %1, %2, %3, {%4,%4,%4,%4}, p;\n\t}"
        :: "r"(d), "l"(a), "l"(b), "r"(idesc), "r"(0u), "r"(en) : "memory");
}
#endif

// idesc: F32 accum, bf16 A/B, N=128, M=128
#define GEMM_IDESC ((1u<<4)|(1u<<7)|(1u<<10)|((128u/8)<<17)|((128u/16)<<24))

// ---------------------------------------------------------------------------
// fp32 -> bf16 hi/lo split
// ---------------------------------------------------------------------------
__global__ void split_bf16(const float* __restrict__ in,
                           __nv_bfloat16* __restrict__ hi,
                           __nv_bfloat16* __restrict__ lo, int n4) {
    int i = blockIdx.x * blockDim.x + threadIdx.x;
    if (i >= n4) return;
    float4 v = ((const float4*)in)[i];
    __nv_bfloat16 h0 = __float2bfloat16(v.x);
    __nv_bfloat16 h1 = __float2bfloat16(v.y);
    __nv_bfloat16 h2 = __float2bfloat16(v.z);
    __nv_bfloat16 h3 = __float2bfloat16(v.w);
    __nv_bfloat162* hp = (__nv_bfloat162*)hi;
    __nv_bfloat162* lp = (__nv_bfloat162*)lo;
    hp[i * 2 + 0] = __halves2bfloat162(h0, h1);
    hp[i * 2 + 1] = __halves2bfloat162(h2, h3);
    lp[i * 2 + 0] = __halves2bfloat162(
        __float2bfloat16(v.x - __bfloat162float(h0)),
        __float2bfloat16(v.y - __bfloat162float(h1)));
    lp[i * 2 + 1] = __halves2bfloat162(
        __float2bfloat16(v.z - __bfloat162float(h2)),
        __float2bfloat16(v.w - __bfloat162float(h3)));
}

// ---------------------------------------------------------------------------
// RoPE + scale + hi/lo split
// ---------------------------------------------------------------------------
__global__ void rope_split(const float* __restrict__ X,
                           __nv_bfloat16* __restrict__ Xh,
                           __nv_bfloat16* __restrict__ Xl,
                           const float* __restrict__ cs,
                           const float* __restrict__ sn,
                           int nheads, float scale) {
    int pps = nheads * (HD / 2);
    int total = SEQ * pps;
    int idx = blockIdx.x * blockDim.x + threadIdx.x;
    if (idx >= total) return;
    int s = idx / pps;
    int r = idx - s * pps;
    int p = r & 63;
    float2 v = ((const float2*)X)[idx];
    float c = cs[s * 64 + p], si = sn[s * 64 + p];
    float o0 = (v.x * c - v.y * si) * scale;
    float o1 = (v.x * si + v.y * c) * scale;
    __nv_bfloat16 h0 = __float2bfloat16(o0);
    __nv_bfloat16 h1 = __float2bfloat16(o1);
    ((__nv_bfloat162*)Xh)[idx] = __halves2bfloat162(h0, h1);
    ((__nv_bfloat162*)Xl)[idx] = __halves2bfloat162(
        __float2bfloat16(o0 - __bfloat162float(h0)),
        __float2bfloat16(o1 - __bfloat162float(h1)));
}

// ---------------------------------------------------------------------------
// Dual-path GEMM (NT): C[M,N]=A@B^T via 3-term bf16 split.
// 128x128 tile. SW128-swizzled smem, 3-stage cp.async ring (64-K per stage).
// Consumer: tcgen05 (if compiled for sm_103a) else mma.sync.
// ---------------------------------------------------------------------------
#define GT_STAGE_BYTES 65536           // 4 arrays x 16KB (128 rows x 128B SW128)
#define GT_NSTG 3
#define GT_SMEM (1024 + GT_NSTG * GT_STAGE_BYTES + 64)

// producer: fill one 64-K stage (4 arrays) — shared by both paths
__device__ __forceinline__ void gt_stage(
    const __nv_bfloat16* Ah, const __nv_bfloat16* Al,
    const __nv_bfloat16* Bh, const __nv_bfloat16* Bl,
    uint32_t sbase, int m0, int n0, int K, int kc, int tid) {
#pragma unroll
    for (int i = 0; i < 4; ++i) {
        int c = tid + 256 * i;            // 0..1023 chunks of 16B
        int row = c >> 3, col = c & 7;
        int so = row * 128 + (((col ^ (row & 7))) << 4);
        long ga = (long)(m0 + row) * K + kc + col * 8;
        long gb = (long)(n0 + row) * K + kc + col * 8;
        cp16(sbase + so,          Ah + ga);
        cp16(sbase + 16384 + so,  Al + ga);
        cp16(sbase + 32768 + so,  Bh + gb);
        cp16(sbase + 49152 + so,  Bl + gb);
    }
    cp_commit();
}

__global__ __launch_bounds__(256, 1)
void gemm_tc(const __nv_bfloat16* __restrict__ Ah,
             const __nv_bfloat16* __restrict__ Al,
             const __nv_bfloat16* __restrict__ Bh,
             const __nv_bfloat16* __restrict__ Bl,
             float* __restrict__ C, int M, int N, int K) {
    extern __shared__ char smg_raw[];
    uint32_t u = smaddr(smg_raw);
    uint32_t t0 = (u + 1023u) & ~1023u;
    const int tid = threadIdx.x;
    const int wid = tid >> 5;
    const int lane = tid & 31;
    const int m0 = blockIdx.y * 128;
    const int n0 = blockIdx.x * 128;
    const int nst = K >> 6;

#if HAS_TCGEN05
    // ======================= tcgen05 path ====================================
    uint32_t ctrl = t0 + GT_NSTG * GT_STAGE_BYTES;
    uint32_t mb[GT_NSTG] = {ctrl + 8, ctrl + 16, ctrl + 24};

    if (wid == 0) {
        TCGEN05_ALLOC(ctrl, 128);
        TCGEN05_RELINQ();
    }
    if (tid == 0) {
        MBARRIER_INIT(mb[0], 1);
        MBARRIER_INIT(mb[1], 1);
        MBARRIER_INIT(mb[2], 1);
    }
    __syncthreads();
    uint32_t tmem;
    asm volatile("ld.shared.b32 %0, [%1];" : "=r"(tmem) : "r"(ctrl));

    gt_stage(Ah, Al, Bh, Bl, t0 + 0 * GT_STAGE_BYTES, m0, n0, K, 0,  tid);
    gt_stage(Ah, Al, Bh, Bl, t0 + 1 * GT_STAGE_BYTES, m0, n0, K, 64, tid);

    for (int t = 0; t < nst; ++t) {
        if (t + 2 < nst) {
            int b2 = (t + 2) % GT_NSTG;
            if (t >= 1) MBARRIER_WAIT_PARITY(mb[b2], ((t - 1) / GT_NSTG) & 1);
            gt_stage(Ah, Al, Bh, Bl, t0 + b2 * GT_STAGE_BYTES, m0, n0, K,
                     (t + 2) * 64, tid);
        }
        if (t + 2 < nst)      asm volatile("cp.async.wait_group 2;");
        else if (t + 1 < nst) asm volatile("cp.async.wait_group 1;");
        else                  asm volatile("cp.async.wait_group 0;");
        FENCE_ASYNC();
        __syncthreads();

        if (tid == 0) {
            TCGEN05_FENCE_AFTER();
            uint32_t base = t0 + (t % GT_NSTG) * GT_STAGE_BYTES;
            uint64_t dAh = MAKE_SMEM_DESC(base);
            uint64_t dAl = MAKE_SMEM_DESC(base + 16384);
            uint64_t dBh = MAKE_SMEM_DESC(base + 32768);
            uint64_t dBl = MAKE_SMEM_DESC(base + 49152);
#pragma unroll
            for (int s = 0; s < 4; ++s) {
                umma_f16_ss(tmem, dAh + 2 * s, dBh + 2 * s, GEMM_IDESC,
                            (t == 0 && s == 0) ? 0u : 1u);
                umma_f16_ss(tmem, dAh + 2 * s, dBl + 2 * s, GEMM_IDESC, 1u);
                umma_f16_ss(tmem, dAl + 2 * s, dBh + 2 * s, GEMM_IDESC, 1u);
            }
            TCGEN05_COMMIT(mb[t % GT_NSTG]);
        }
    }

    const int lastb = (nst - 1) % GT_NSTG;
    const int lastp = ((nst - 1) / GT_NSTG) & 1;
    MBARRIER_WAIT_PARITY(mb[lastb], lastp);
    TCGEN05_FENCE_AFTER();

    // epilogue: warps 0-3 -> cols 0..63, warps 4-7 -> cols 64..127
    {
        int row = m0 + (wid & 3) * 32 + lane;
        int cb  = (wid >> 2) * 64;
#pragma unroll
        for (int cc = 0; cc < 2; ++cc) {
            uint32_t r[32];
            TCGEN05_LD_X32(r, tmem + cb + cc * 32);
            TCGEN05_WAIT_LD();
            float* dst = &C[(long)row * N + n0 + cb + cc * 32];
#pragma unroll
            for (int q = 0; q < 8; ++q) {
                *(float4*)(dst + q * 4) = make_float4(
                    __uint_as_float(r[q * 4 + 0]), __uint_as_float(r[q * 4 + 1]),
                    __uint_as_float(r[q * 4 + 2]), __uint_as_float(r[q * 4 + 3]));
            }
        }
    }
    __syncthreads();
    if (wid == 0) TCGEN05_DEALLOC(tmem, 128);

#else
    // ======================= mma.sync fallback ===============================
    const int wm = (wid >> 1) * 32;
    const int wn = (wid & 1) * 64;

    float acc[2][8][4];
#pragma unroll
    for (int i = 0; i < 2; ++i)
#pragma unroll
        for (int j = 0; j < 8; ++j)
#pragma unroll
            for (int q = 0; q < 4; ++q) acc[i][j][q] = 0.0f;

    gt_stage(Ah, Al, Bh, Bl, t0 + 0 * GT_STAGE_BYTES, m0, n0, K, 0,  tid);
    gt_stage(Ah, Al, Bh, Bl, t0 + 1 * GT_STAGE_BYTES, m0, n0, K, 64, tid);

    for (int t = 0; t < nst; ++t) {
        if (t + 2 < nst) {
            // buffer (t+2)%3 was fully consumed at iteration t-1 (syncthreads'd)
            gt_stage(Ah, Al, Bh, Bl, t0 + ((t + 2) % GT_NSTG) * GT_STAGE_BYTES,
                     m0, n0, K, (t + 2) * 64, tid);
        }
        if (t + 2 < nst)      asm volatile("cp.async.wait_group 2;");
        else if (t + 1 < nst) asm volatile("cp.async.wait_group 1;");
        else                  asm volatile("cp.async.wait_group 0;");
        __syncthreads();

        uint32_t base = t0 + (t % GT_NSTG) * GT_STAGE_BYTES;
#pragma unroll
        for (int kb = 0; kb < 4; ++kb) {
            uint32_t ah[2][4], al[2][4];
#pragma unroll
            for (int mf = 0; mf < 2; ++mf) {
                int arow = wm + mf * 16 + (lane & 15);
                int col8 = kb * 2 + (lane >> 4);
                uint32_t off = arow * 128 + ((col8 ^ (arow & 7)) << 4);
                ldsm4(ah[mf][0], ah[mf][1], ah[mf][2], ah[mf][3], base + off);
                ldsm4(al[mf][0], al[mf][1], al[mf][2], al[mf][3],
                      base + 16384 + off);
            }
#pragma unroll
            for (int np = 0; np < 4; ++np) {
                int brow = wn + np * 16 + (lane & 7) + ((lane >> 4) << 3);
                int col8 = kb * 2 + ((lane >> 3) & 1);
                uint32_t off = brow * 128 + ((col8 ^ (brow & 7)) << 4);
                uint32_t bh[4], bl[4];
                ldsm4(bh[0], bh[1], bh[2], bh[3], base + 32768 + off);
                ldsm4(bl[0], bl[1], bl[2], bl[3], base + 49152 + off);
#pragma unroll
                for (int hf = 0; hf < 2; ++hf) {
                    int nf = np * 2 + hf;
#pragma unroll
                    for (int mf = 0; mf < 2; ++mf) {
                        mma16816(acc[mf][nf], ah[mf], bh[hf * 2], bh[hf * 2 + 1]);
                        mma16816(acc[mf][nf], ah[mf], bl[hf * 2], bl[hf * 2 + 1]);
                        mma16816(acc[mf][nf], al[mf], bh[hf * 2], bh[hf * 2 + 1]);
                    }
                }
            }
        }
        __syncthreads();
    }

#pragma unroll
    for (int mf = 0; mf < 2; ++mf) {
        int row = m0 + wm + mf * 16 + (lane >> 2);
#pragma unroll
        for (int nf = 0; nf < 8; ++nf) {
            int col = n0 + wn + nf * 8 + (lane & 3) * 2;
            *(float2*)&C[(long)row * N + col] =
                make_float2(acc[mf][nf][0], acc[mf][nf][1]);
            *(float2*)&C[(long)(row + 8) * N + col] =
                make_float2(acc[mf][nf][2], acc[mf][nf][3]);
        }
    }
#endif
}

// ---------------------------------------------------------------------------
// Tensor-core flash attention (mma.sync, causal, GQA 4:1) — proven R2 version.
// ---------------------------------------------------------------------------
#define ATT_TS (64 * PADK)
#define ATT_SMEM (8 * ATT_TS * 2)

__device__ __forceinline__ void attn_issue(
    const __nv_bfloat16* Kh_, const __nv_bfloat16* Kl_,
    const __nv_bfloat16* Vh_, const __nv_bfloat16* Vl_,
    __nv_bfloat16* sKh, __nv_bfloat16* sKl,
    __nv_bfloat16* sVh, __nv_bfloat16* sVl,
    int j0, int kvh, int tid) {
#pragma unroll
    for (int i = 0; i < 4; ++i) {
        int c = tid + 256 * i;
        int row = c >> 4, c16 = c & 15;
        long g = (long)(j0 + row) * KV_DIM + kvh * HD + c16 * 8;
        int so = row * PADK + c16 * 8;
        cp16(smaddr(sKh + so), Kh_ + g);
        cp16(smaddr(sKl + so), Kl_ + g);
        cp16(smaddr(sVh + so), Vh_ + g);
        cp16(smaddr(sVl + so), Vl_ + g);
    }
    cp_commit();
}

__global__ __launch_bounds__(256, 1)
void attn_mma(const __nv_bfloat16* __restrict__ Qh,
              const __nv_bfloat16* __restrict__ Ql,
              const __nv_bfloat16* __restrict__ Kh_,
              const __nv_bfloat16* __restrict__ Kl_,
              const __nv_bfloat16* __restrict__ Vh_,
              const __nv_bfloat16* __restrict__ Vl_,
              float* __restrict__ O) {
    extern __shared__ __nv_bfloat16 sma[];
    __nv_bfloat16* sKh[2] = {sma + 0 * ATT_TS, sma + 1 * ATT_TS};
    __nv_bfloat16* sKl[2] = {sma + 2 * ATT_TS, sma + 3 * ATT_TS};
    __nv_bfloat16* sVh[2] = {sma + 4 * ATT_TS, sma + 5 * ATT_TS};
    __nv_bfloat16* sVl[2] = {sma + 6 * ATT_TS, sma + 7 * ATT_TS};

    const int tid = threadIdx.x;
    const int lane = tid & 31;
    const int w = tid >> 5;
    const int g = lane >> 2;
    const int qq = lane & 3;
    const int h = blockIdx.y;
    const int kvh = h >> 2;
    const int qt = gridDim.x - 1 - blockIdx.x;
    const int q0 = qt * BQT;

    const int r0 = q0 + w * 16 + g;
    const int r1 = r0 + 8;
    uint32_t qfh[8][4], qfl[8][4];
#pragma unroll
    for (int k = 0; k < 8; ++k) {
        int c = h * HD + k * 16 + qq * 2;
        qfh[k][0] = *(const uint32_t*)&Qh[(long)r0 * DIM + c];
        qfh[k][1] = *(const uint32_t*)&Qh[(long)r1 * DIM + c];
        qfh[k][2] = *(const uint32_t*)&Qh[(long)r0 * DIM + c + 8];
        qfh[k][3] = *(const uint32_t*)&Qh[(long)r1 * DIM + c + 8];
        qfl[k][0] = *(const uint32_t*)&Ql[(long)r0 * DIM + c];
        qfl[k][1] = *(const uint32_t*)&Ql[(long)r1 * DIM + c];
        qfl[k][2] = *(const uint32_t*)&Ql[(long)r0 * DIM + c + 8];
        qfl[k][3] = *(const uint32_t*)&Ql[(long)r1 * DIM + c + 8];
    }

    float of[16][4];
#pragma unroll
    for (int i = 0; i < 16; ++i)
#pragma unroll
        for (int j = 0; j < 4; ++j) of[i][j] = 0.0f;
    float m0 = -1e30f, m1 = -1e30f, l0 = 0.0f, l1 = 0.0f;

    const int nt = 2 * qt + 2;
    attn_issue(Kh_, Kl_, Vh_, Vl_, sKh[0], sKl[0], sVh[0], sVl[0], 0, kvh, tid);

    for (int t = 0; t < nt; ++t) {
        if (t + 1 < nt) {
            int bb = (t + 1) & 1;
            attn_issue(Kh_, Kl_, Vh_, Vl_, sKh[bb], sKl[bb], sVh[bb], sVl[bb],
                       (t + 1) * BKT, kvh, tid);
            asm volatile("cp.async.wait_group 1;");
        } else {
            asm volatile("cp.async.wait_group 0;");
        }
        __syncthreads();
        const int buf = t & 1;
        const int j0 = t * BKT;

        float sc[8][4];
#pragma unroll
        for (int i = 0; i < 8; ++i)
#pragma unroll
            for (int j = 0; j < 4; ++j) sc[i][j] = 0.0f;

#pragma unroll
        for (int k = 0; k < 8; ++k) {
#pragma unroll
            for (int np = 0; np < 4; ++np) {
                int brow = np * 16 + (lane & 7) + ((lane >> 4) << 3);
                int bcol = k * 16 + (((lane >> 3) & 1) << 3);
                uint32_t bh[4], bl[4];
                ldsm4(bh[0], bh[1], bh[2], bh[3],
                      smaddr(sKh[buf] + brow * PADK + bcol));
                ldsm4(bl[0], bl[1], bl[2], bl[3],
                      smaddr(sKl[buf] + brow * PADK + bcol));
#pragma unroll
                for (int hf = 0; hf < 2; ++hf) {
                    int nf = np * 2 + hf;
                    mma16816(sc[nf], qfh[k], bh[hf * 2], bh[hf * 2 + 1]);
                    mma16816(sc[nf], qfh[k], bl[hf * 2], bl[hf * 2 + 1]);
                    mma16816(sc[nf], qfl[k], bh[hf * 2], bh[hf * 2 + 1]);
                }
            }
        }

        if (t >= nt - 2) {
#pragma unroll
            for (int nf = 0; nf < 8; ++nf) {
                int cb = j0 + nf * 8 + qq * 2;
                if (cb > r0)     sc[nf][0] = -1e30f;
                if (cb + 1 > r0) sc[nf][1] = -1e30f;
                if (cb > r1)     sc[nf][2] = -1e30f;
                if (cb + 1 > r1) sc[nf][3] = -1e30f;
            }
        }

        float mt0 = -1e30f, mt1 = -1e30f;
#pragma unroll
        for (int nf = 0; nf < 8; ++nf) {
            mt0 = fmaxf(mt0, fmaxf(sc[nf][0], sc[nf][1]));
            mt1 = fmaxf(mt1, fmaxf(sc[nf][2], sc[nf][3]));
        }
        mt0 = fmaxf(mt0, __shfl_xor_sync(0xffffffff, mt0, 1));
        mt0 = fmaxf(mt0, __shfl_xor_sync(0xffffffff, mt0, 2));
        mt1 = fmaxf(mt1, __shfl_xor_sync(0xffffffff, mt1, 1));
        mt1 = fmaxf(mt1, __shfl_xor_sync(0xffffffff, mt1, 2));
        float mn0 = fmaxf(m0, mt0), mn1 = fmaxf(m1, mt1);
        float a0 = __expf(m0 - mn0), a1 = __expf(m1 - mn1);
        m0 = mn0; m1 = mn1;

        float rs0 = 0.0f, rs1 = 0.0f;
#pragma unroll
        for (int nf = 0; nf < 8; ++nf) {
            sc[nf][0] = __expf(sc[nf][0] - mn0); rs0 += sc[nf][0];
            sc[nf][1] = __expf(sc[nf][1] - mn0); rs0 += sc[nf][1];
            sc[nf][2] = __expf(sc[nf][2] - mn1); rs1 += sc[nf][2];
            sc[nf][3] = __expf(sc[nf][3] - mn1); rs1 += sc[nf][3];
        }
        rs0 += __shfl_xor_sync(0xffffffff, rs0, 1);
        rs0 += __shfl_xor_sync(0xffffffff, rs0, 2);
        rs1 += __shfl_xor_sync(0xffffffff, rs1, 1);
        rs1 += __shfl_xor_sync(0xffffffff, rs1, 2);
        l0 = l0 * a0 + rs0;
        l1 = l1 * a1 + rs1;

#pragma unroll
        for (int nf = 0; nf < 16; ++nf) {
            of[nf][0] *= a0; of[nf][1] *= a0;
            of[nf][2] *= a1; of[nf][3] *= a1;
        }

#pragma unroll
        for (int ks = 0; ks < 4; ++ks) {
            uint32_t ph[4], pl[4];
            {
                float s00 = sc[2 * ks][0],     s01 = sc[2 * ks][1];
                float s02 = sc[2 * ks][2],     s03 = sc[2 * ks][3];
                float s10 = sc[2 * ks + 1][0], s11 = sc[2 * ks + 1][1];
                float s12 = sc[2 * ks + 1][2], s13 = sc[2 * ks + 1][3];
                ph[0] = bpack(s00, s01); ph[1] = bpack(s02, s03);
                ph[2] = bpack(s10, s11); ph[3] = bpack(s12, s13);
                __nv_bfloat162* hp;
                hp = (__nv_bfloat162*)&ph[0];
                pl[0] = bpack(s00 - __bfloat162float(hp->x), s01 - __bfloat162float(hp->y));
                hp = (__nv_bfloat162*)&ph[1];
                pl[1] = bpack(s02 - __bfloat162float(hp->x), s03 - __bfloat162float(hp->y));
                hp = (__nv_bfloat162*)&ph[2];
                pl[2] = bpack(s10 - __bfloat162float(hp->x), s11 - __bfloat162float(hp->y));
                hp = (__nv_bfloat162*)&ph[3];
                pl[3] = bpack(s12 - __bfloat162float(hp->x), s13 - __bfloat162float(hp->y));
            }
            int vrow = ks * 16 + (lane & 7) + (((lane >> 3) & 1) << 3);
#pragma unroll
            for (int nn = 0; nn < 8; ++nn) {
                int vcol = nn * 16 + ((lane >> 4) << 3);
                uint32_t vh[4], vl[4];
                ldsm4t(vh[0], vh[1], vh[2], vh[3],
                       smaddr(sVh[buf] + vrow * PADK + vcol));
                ldsm4t(vl[0], vl[1], vl[2], vl[3],
                       smaddr(sVl[buf] + vrow * PADK + vcol));
                mma16816(of[nn * 2], ph, vh[0], vh[1]);
                mma16816(of[nn * 2], ph, vl[0], vl[1]);
                mma16816(of[nn * 2], pl, vh[0], vh[1]);
                mma16816(of[nn * 2 + 1], ph, vh[2], vh[3]);
                mma16816(of[nn * 2 + 1], ph, vl[2], vl[3]);
                mma16816(of[nn * 2 + 1], pl, vh[2], vh[3]);
            }
        }
        __syncthreads();
    }

    float inv0 = 1.0f / l0, inv1 = 1.0f / l1;
#pragma unroll
    for (int nf = 0; nf < 16; ++nf) {
        int col = h * HD + nf * 8 + qq * 2;
        *(float2*)&O[(long)r0 * DIM + col] =
            make_float2(of[nf][0] * inv0, of[nf][1] * inv0);
        *(float2*)&O[(long)r1 * DIM + col] =
            make_float2(of[nf][2] * inv1, of[nf][3] * inv1);
    }
}

// ---------------------------------------------------------------------------
// Launcher
// ---------------------------------------------------------------------------
extern "C" void kernel_launch(void* const* d_in, const int* in_sizes, int n_in,
                              void* d_out, int out_size) {
    const float* x  = (const float*)d_in[0];
    const float* wq = (const float*)d_in[1];
    const float* wk = (const float*)d_in[2];
    const float* wv = (const float*)d_in[3];
    const float* wo = (const float*)d_in[4];
    const float* fc = (const float*)d_in[5];
    const float* fs = (const float*)d_in[6];
    float* out = (float*)d_out;

    float *Qp, *Kp, *Vp, *Op;
    cudaGetSymbolAddress((void**)&Qp, g_Q);
    cudaGetSymbolAddress((void**)&Kp, g_K);
    cudaGetSymbolAddress((void**)&Vp, g_V);
    cudaGetSymbolAddress((void**)&Op, g_O);

    __nv_bfloat16 *xh, *xl, *wqh, *wql, *wkh, *wkl, *wvh, *wvl, *woh, *wol, *oh, *ol;
    __nv_bfloat16 *qh, *ql, *kh, *kl, *vh, *vl;
    cudaGetSymbolAddress((void**)&xh,  g_xh);  cudaGetSymbolAddress((void**)&xl,  g_xl);
    cudaGetSymbolAddress((void**)&wqh, g_wqh); cudaGetSymbolAddress((void**)&wql, g_wql);
    cudaGetSymbolAddress((void**)&wkh, g_wkh); cudaGetSymbolAddress((void**)&wkl, g_wkl);
    cudaGetSymbolAddress((void**)&wvh, g_wvh); cudaGetSymbolAddress((void**)&wvl, g_wvl);
    cudaGetSymbolAddress((void**)&woh, g_woh); cudaGetSymbolAddress((void**)&wol, g_wol);
    cudaGetSymbolAddress((void**)&oh,  g_oh);  cudaGetSymbolAddress((void**)&ol,  g_ol);
    cudaGetSymbolAddress((void**)&qh,  g_Qh);  cudaGetSymbolAddress((void**)&ql,  g_Ql);
    cudaGetSymbolAddress((void**)&kh,  g_Kh);  cudaGetSymbolAddress((void**)&kl,  g_Kl);
    cudaGetSymbolAddress((void**)&vh,  g_Vh);  cudaGetSymbolAddress((void**)&vl,  g_Vl);

    cudaFuncSetAttribute(gemm_tc,
                         cudaFuncAttributeMaxDynamicSharedMemorySize, GT_SMEM);
    cudaFuncSetAttribute(attn_mma,
                         cudaFuncAttributeMaxDynamicSharedMemorySize, ATT_SMEM);

    auto launch_split = [](const float* in, __nv_bfloat16* hi, __nv_bfloat16* lo, int n) {
        int n4 = n / 4;
        split_bf16<<<(n4 + 255) / 256, 256>>>(in, hi, lo, n4);
    };
    launch_split(x,  xh,  xl,  SEQ * DIM);
    launch_split(wq, wqh, wql, DIM * DIM);
    launch_split(wk, wkh, wkl, KV_DIM * DIM);
    launch_split(wv, wvh, wvl, KV_DIM * DIM);
    launch_split(wo, woh, wol, DIM * DIM);

    // Projections
    gemm_tc<<<dim3(DIM / 128,    SEQ / 128), 256, GT_SMEM>>>(xh, xl, wqh, wql, Qp, SEQ, DIM,    DIM);
    gemm_tc<<<dim3(KV_DIM / 128, SEQ / 128), 256, GT_SMEM>>>(xh, xl, wkh, wkl, Kp, SEQ, KV_DIM, DIM);
    gemm_tc<<<dim3(KV_DIM / 128, SEQ / 128), 256, GT_SMEM>>>(xh, xl, wvh, wvl, Vp, SEQ, KV_DIM, DIM);

    // RoPE + split (Q pre-scaled); V split
    int qpairs = SEQ * NH * (HD / 2);
    int kpairs = SEQ * NKV * (HD / 2);
    rope_split<<<(qpairs + 255) / 256, 256>>>(Qp, qh, ql, fc, fs, NH, 0.08838834764831845f);
    rope_split<<<(kpairs + 255) / 256, 256>>>(Kp, kh, kl, fc, fs, NKV, 1.0f);
    launch_split(Vp, vh, vl, SEQ * KV_DIM);

    // Flash attention
    attn_mma<<<dim3(SEQ / BQT, NH), 256, ATT_SMEM>>>(qh, ql, kh, kl, vh, vl, Op);

    // Output projection
    launch_split(Op, oh, ol, SEQ * DIM);
    gemm_tc<<<dim3(DIM / 128, SEQ / 128), 256, GT_SMEM>>>(oh, ol, woh, wol, out, SEQ, DIM, DIM);
}

// round 6
// speedup vs baseline: 6.6515x; 1.0995x over previous
#include <cuda_runtime.h>
#include <cuda_bf16.h>
#include <stdint.h>

#define SEQ    2048
#define DIM    4096
#define NH     32
#define NKV    8
#define HD     128
#define KV_DIM 1024
#define BQT    128
#define BKT    64
#define PADK   136

#if defined(__CUDA_ARCH_FEAT_SM103_ALL) || defined(__CUDA_ARCH_FEAT_SM100_ALL)
#define HAS_TCGEN05 1
#else
#define HAS_TCGEN05 0
#endif

// ---------------------------------------------------------------------------
// Static device scratch
// ---------------------------------------------------------------------------
__device__ float g_Q[SEQ * DIM];
__device__ float g_K[SEQ * KV_DIM];
__device__ float g_V[SEQ * KV_DIM];

__device__ __nv_bfloat16 g_xh[SEQ * DIM],     g_xl[SEQ * DIM];
__device__ __nv_bfloat16 g_wqh[DIM * DIM],    g_wql[DIM * DIM];
__device__ __nv_bfloat16 g_wkh[KV_DIM * DIM], g_wkl[KV_DIM * DIM];
__device__ __nv_bfloat16 g_wvh[KV_DIM * DIM], g_wvl[KV_DIM * DIM];
__device__ __nv_bfloat16 g_woh[DIM * DIM],    g_wol[DIM * DIM];
__device__ __nv_bfloat16 g_oh[SEQ * DIM],     g_ol[SEQ * DIM];

__device__ __nv_bfloat16 g_Qh[SEQ * DIM],     g_Ql[SEQ * DIM];
__device__ __nv_bfloat16 g_Kh[SEQ * KV_DIM],  g_Kl[SEQ * KV_DIM];
__device__ __nv_bfloat16 g_Vh[SEQ * KV_DIM],  g_Vl[SEQ * KV_DIM];

// ---------------------------------------------------------------------------
// Helpers
// ---------------------------------------------------------------------------
__device__ __forceinline__ uint32_t smaddr(const void* p) {
    return (uint32_t)__cvta_generic_to_shared(p);
}
__device__ __forceinline__ void cp16(uint32_t s, const void* g) {
    asm volatile("cp.async.cg.shared.global [%0], [%1], 16;" :: "r"(s), "l"(g));
}
__device__ __forceinline__ void cp_commit() {
    asm volatile("cp.async.commit_group;");
}
__device__ __forceinline__ void ldsm4(uint32_t& r0, uint32_t& r1,
                                      uint32_t& r2, uint32_t& r3, uint32_t a) {
    asm volatile("ldmatrix.sync.aligned.m8n8.x4.shared.b16 {%0,%1,%2,%3}, [%4];"
                 : "=r"(r0), "=r"(r1), "=r"(r2), "=r"(r3) : "r"(a));
}
__device__ __forceinline__ void ldsm4t(uint32_t& r0, uint32_t& r1,
                                       uint32_t& r2, uint32_t& r3, uint32_t a) {
    asm volatile("ldmatrix.sync.aligned.m8n8.x4.trans.shared.b16 {%0,%1,%2,%3}, [%4];"
                 : "=r"(r0), "=r"(r1), "=r"(r2), "=r"(r3) : "r"(a));
}
__device__ __forceinline__ void mma16816(float* c, const uint32_t* a,
                                         uint32_t b0, uint32_t b1) {
    asm volatile(
        "mma.sync.aligned.m16n8k16.row.col.f32.bf16.bf16.f32 "
        "{%0,%1,%2,%3},{%4,%5,%6,%7},{%8,%9},{%0,%1,%2,%3};"
        : "+f"(c[0]), "+f"(c[1]), "+f"(c[2]), "+f"(c[3])
        : "r"(a[0]), "r"(a[1]), "r"(a[2]), "r"(a[3]), "r"(b0), "r"(b1));
}
__device__ __forceinline__ uint32_t bpack(float a, float b) {
    __nv_bfloat162 v;
    v.x = __float2bfloat16(a);
    v.y = __float2bfloat16(b);
    return *(uint32_t*)&v;
}

// ---- tcgen05 -----------------------------------------------------------------
static constexpr uint64_t SMEM_DESC_BASE_SW128 =
    (uint64_t(2)  << 61) | (uint64_t(1) << 46) |
    (uint64_t(64) << 32) | (uint64_t(1) << 16);
#define MAKE_SMEM_DESC(base_addr) \
    (SMEM_DESC_BASE_SW128 | ((uint64_t)((base_addr) >> 4) & 0x3FFF))

#define MBARRIER_INIT(mbar, count) \
    asm volatile("mbarrier.init.shared.b64 [%0], %1;" \
                 :: "r"((uint32_t)(mbar)), "r"((uint32_t)(count)) : "memory")
#define FENCE_ASYNC() \
    asm volatile("fence.proxy.async.shared::cta;" ::: "memory")

#define MBARRIER_WAIT_PARITY(mbar_smem_addr, phase_parity) do { \
    uint32_t _mbar = (uint32_t)(mbar_smem_addr); \
    uint32_t _parity = (uint32_t)(phase_parity); \
    uint32_t _done; \
    asm volatile( \
        "{\n\t.reg .pred p;\n\t" \
        "mbarrier.try_wait.parity.acquire.cta.shared::cta.b64 p, [%1], %2;\n\t" \
        "selp.b32 %0, 1, 0, p;\n\t}" \
        : "=r"(_done) : "r"(_mbar), "r"(_parity) : "memory"); \
    if (!_done) { \
        asm volatile( \
            "{\n\t.reg .pred P1;\n\t" \
            "WAIT_LOOP_%=:\n\t" \
            "mbarrier.try_wait.parity.acquire.cta.shared::cta.b64 P1, [%0], %1, 0x989680;\n\t" \
            "@P1 bra.uni WAIT_DONE_%=;\n\t" \
            "bra.uni WAIT_LOOP_%=;\n\t" \
            "WAIT_DONE_%=:\n\t}" \
            :: "r"(_mbar), "r"(_parity) : "memory"); \
    } \
} while(0)

#if HAS_TCGEN05
#define TCGEN05_ALLOC(smem_result_addr, nCols) \
    asm volatile("tcgen05.alloc.cta_group::1.sync.aligned.shared::cta.b32 [%0], %1;" \
                 :: "r"((uint32_t)(smem_result_addr)), "r"((uint32_t)(nCols)) : "memory")
#define TCGEN05_DEALLOC(tmem_addr, nCols) \
    asm volatile("tcgen05.dealloc.cta_group::1.sync.aligned.b32 %0, %1;" \
                 :: "r"(tmem_addr), "r"((uint32_t)(nCols)))
#define TCGEN05_RELINQ() \
    asm volatile("tcgen05.relinquish_alloc_permit.cta_group::1.sync.aligned;")
#define TCGEN05_COMMIT(mbar) \
    asm volatile("tcgen05.commit.cta_group::1.mbarrier::arrive::one.shared::cluster.b64 [%0];" \
                 :: "r"((uint32_t)(mbar)) : "memory")
#define TCGEN05_FENCE_AFTER() \
    asm volatile("tcgen05.fence::after_thread_sync;" ::: "memory")
#define TCGEN05_WAIT_LD() \
    asm volatile("tcgen05.wait::ld.sync.aligned;" ::: "memory")
#define TCGEN05_LD_X32(r, tmem_addr) \
    asm volatile( \
        "tcgen05.ld.sync.aligned.32x32b.x32.b32 " \
        "{%0, %1, %2, %3, %4, %5, %6, %7, " \
        " %8, %9, %10, %11, %12, %13, %14, %15, " \
        " %16, %17, %18, %19, %20, %21, %22, %23, " \
        " %24, %25, %26, %27, %28, %29, %30, %31}, [%32];" \
        : "=r"((r)[0]),  "=r"((r)[1]),  "=r"((r)[2]),  "=r"((r)[3]), \
          "=r"((r)[4]),  "=r"((r)[5]),  "=r"((r)[6]),  "=r"((r)[7]), \
          "=r"((r)[8]),  "=r"((r)[9]),  "=r"((r)[10]), "=r"((r)[11]), \
          "=r"((r)[12]), "=r"((r)[13]), "=r"((r)[14]), "=r"((r)[15]), \
          "=r"((r)[16]), "=r"((r)[17]), "=r"((r)[18]), "=r"((r)[19]), \
          "=r"((r)[20]), "=r"((r)[21]), "=r"((r)[22]), "=r"((r)[23]), \
          "=r"((r)[24]), "=r"((r)[25]), "=r"((r)[26]), "=r"((r)[27]), \
          "=r"((r)[28]), "=r"((r)[29]), "=r"((r)[30]), "=r"((r)[31]) \
        : "r"(tmem_addr))

__device__ __forceinline__ void umma_f16_ss(uint32_t d, uint64_t a, uint64_t b,
                                            uint32_t idesc, uint32_t en) {
    asm volatile(
        "{\n\t.reg .pred p;\n\t"
        "setp.ne.u32 p, %5, 0;\n\t"
        "tcgen05.mma.cta_group::1.kind::f16 [%0], %1, %2, %3, {%4,%4,%4,%4}, p;\n\t}"
        :: "r"(d), "l"(a), "l"(b), "r"(idesc), "r"(0u), "r"(en) : "memory");
}
#endif

// idesc: F32 accum, bf16 A/B, N=128, M=128 (proven in R5)
#define GEMM_IDESC ((1u<<4)|(1u<<7)|(1u<<10)|((128u/8)<<17)|((128u/16)<<24))

// ---------------------------------------------------------------------------
// fp32 -> bf16 hi/lo split
// ---------------------------------------------------------------------------
__global__ void split_bf16(const float* __restrict__ in,
                           __nv_bfloat16* __restrict__ hi,
                           __nv_bfloat16* __restrict__ lo, int n4) {
    int i = blockIdx.x * blockDim.x + threadIdx.x;
    if (i >= n4) return;
    float4 v = ((const float4*)in)[i];
    __nv_bfloat16 h0 = __float2bfloat16(v.x);
    __nv_bfloat16 h1 = __float2bfloat16(v.y);
    __nv_bfloat16 h2 = __float2bfloat16(v.z);
    __nv_bfloat16 h3 = __float2bfloat16(v.w);
    __nv_bfloat162* hp = (__nv_bfloat162*)hi;
    __nv_bfloat162* lp = (__nv_bfloat162*)lo;
    hp[i * 2 + 0] = __halves2bfloat162(h0, h1);
    hp[i * 2 + 1] = __halves2bfloat162(h2, h3);
    lp[i * 2 + 0] = __halves2bfloat162(
        __float2bfloat16(v.x - __bfloat162float(h0)),
        __float2bfloat16(v.y - __bfloat162float(h1)));
    lp[i * 2 + 1] = __halves2bfloat162(
        __float2bfloat16(v.z - __bfloat162float(h2)),
        __float2bfloat16(v.w - __bfloat162float(h3)));
}

// ---------------------------------------------------------------------------
// RoPE + scale + hi/lo split
// ---------------------------------------------------------------------------
__global__ void rope_split(const float* __restrict__ X,
                           __nv_bfloat16* __restrict__ Xh,
                           __nv_bfloat16* __restrict__ Xl,
                           const float* __restrict__ cs,
                           const float* __restrict__ sn,
                           int nheads, float scale) {
    int pps = nheads * (HD / 2);
    int total = SEQ * pps;
    int idx = blockIdx.x * blockDim.x + threadIdx.x;
    if (idx >= total) return;
    int s = idx / pps;
    int r = idx - s * pps;
    int p = r & 63;
    float2 v = ((const float2*)X)[idx];
    float c = cs[s * 64 + p], si = sn[s * 64 + p];
    float o0 = (v.x * c - v.y * si) * scale;
    float o1 = (v.x * si + v.y * c) * scale;
    __nv_bfloat16 h0 = __float2bfloat16(o0);
    __nv_bfloat16 h1 = __float2bfloat16(o1);
    ((__nv_bfloat162*)Xh)[idx] = __halves2bfloat162(h0, h1);
    ((__nv_bfloat162*)Xl)[idx] = __halves2bfloat162(
        __float2bfloat16(o0 - __bfloat162float(h0)),
        __float2bfloat16(o1 - __bfloat162float(h1)));
}

// ---------------------------------------------------------------------------
// Dual-path GEMM (NT): C[M,N]=A@B^T via 3-term bf16 split.
// Tile 128(M) x 256(N), K-stage 64, 2-stage cp.async ring, SW128 smem.
// Optional second B/C set (dual launch fusion): blocks with
// blockIdx.x >= gridDim.x/2 use (Bh2,Bl2,C2).
// ---------------------------------------------------------------------------
#define GT_ST_A 16384                   // one A array per stage (128 x 128B)
#define GT_ST_B 32768                   // one B array per stage (256 x 128B)
#define GT_STAGE (2*GT_ST_A + 2*GT_ST_B)   // 96 KB
#define GT_SMEM (1024 + 2*GT_STAGE + 64)

__device__ __forceinline__ void gt_stage(
    const __nv_bfloat16* Ah, const __nv_bfloat16* Al,
    const __nv_bfloat16* Bh, const __nv_bfloat16* Bl,
    uint32_t sb, int m0, int n0, int K, int kc, int tid) {
#pragma unroll
    for (int i = 0; i < 4; ++i) {       // A: 128 rows x 8 chunks
        int c = tid + 256 * i;
        int row = c >> 3, col = c & 7;
        int so = row * 128 + ((col ^ (row & 7)) << 4);
        long ga = (long)(m0 + row) * K + kc + col * 8;
        cp16(sb + so,           Ah + ga);
        cp16(sb + GT_ST_A + so, Al + ga);
    }
#pragma unroll
    for (int i = 0; i < 8; ++i) {       // B: 256 rows x 8 chunks
        int c = tid + 256 * i;
        int row = c >> 3, col = c & 7;
        int so = row * 128 + ((col ^ (row & 7)) << 4);
        long gb = (long)(n0 + row) * K + kc + col * 8;
        cp16(sb + 2 * GT_ST_A + so,            Bh + gb);
        cp16(sb + 2 * GT_ST_A + GT_ST_B + so,  Bl + gb);
    }
    cp_commit();
}

__global__ __launch_bounds__(256, 1)
void gemm_tc(const __nv_bfloat16* __restrict__ Ah,
             const __nv_bfloat16* __restrict__ Al,
             const __nv_bfloat16* __restrict__ Bh_,
             const __nv_bfloat16* __restrict__ Bl_,
             float* __restrict__ C_,
             const __nv_bfloat16* __restrict__ Bh2,
             const __nv_bfloat16* __restrict__ Bl2,
             float* __restrict__ C2,
             int M, int N, int K) {
    extern __shared__ char smg_raw[];
    uint32_t u = smaddr(smg_raw);
    uint32_t t0 = (u + 1023u) & ~1023u;
    const int tid = threadIdx.x;
    const int wid = tid >> 5;
    const int lane = tid & 31;
    const int m0 = blockIdx.y * 128;
    const int nst = K >> 6;

    // dual-B select
    const __nv_bfloat16* Bh = Bh_;
    const __nv_bfloat16* Bl = Bl_;
    float* C = C_;
    int bx = blockIdx.x;
    if (C2 != nullptr) {
        int half = gridDim.x >> 1;
        if (bx >= half) { bx -= half; Bh = Bh2; Bl = Bl2; C = C2; }
    }
    const int n0 = bx * 256;

#if HAS_TCGEN05
    // ======================= tcgen05 path ====================================
    uint32_t ctrl = t0 + 2 * GT_STAGE;
    uint32_t mb[2] = {ctrl + 8, ctrl + 16};

    if (wid == 0) {
        TCGEN05_ALLOC(ctrl, 256);
        TCGEN05_RELINQ();
    }
    if (tid == 0) {
        MBARRIER_INIT(mb[0], 1);
        MBARRIER_INIT(mb[1], 1);
    }
    __syncthreads();
    uint32_t tmem;
    asm volatile("ld.shared.b32 %0, [%1];" : "=r"(tmem) : "r"(ctrl));

    gt_stage(Ah, Al, Bh, Bl, t0,            m0, n0, K, 0,  tid);
    gt_stage(Ah, Al, Bh, Bl, t0 + GT_STAGE, m0, n0, K, 64, tid);

    for (int t = 0; t < nst; ++t) {
        if (t + 1 < nst) asm volatile("cp.async.wait_group 1;");
        else             asm volatile("cp.async.wait_group 0;");
        FENCE_ASYNC();
        __syncthreads();

        if (tid == 0) {
            TCGEN05_FENCE_AFTER();
            uint32_t base = t0 + (t & 1) * GT_STAGE;
            uint64_t dAh = MAKE_SMEM_DESC(base);
            uint64_t dAl = MAKE_SMEM_DESC(base + GT_ST_A);
            uint64_t dBh = MAKE_SMEM_DESC(base + 2 * GT_ST_A);
            uint64_t dBl = MAKE_SMEM_DESC(base + 2 * GT_ST_A + GT_ST_B);
#pragma unroll
            for (int s = 0; s < 4; ++s) {
#pragma unroll
                for (int nh = 0; nh < 2; ++nh) {
                    uint64_t bo = (uint64_t)(2 * s + nh * 1024);   // +16KB rows
                    uint32_t dd = tmem + nh * 128;
                    umma_f16_ss(dd, dAh + 2 * s, dBh + bo, GEMM_IDESC,
                                (t == 0 && s == 0) ? 0u : 1u);
                    umma_f16_ss(dd, dAh + 2 * s, dBl + bo, GEMM_IDESC, 1u);
                    umma_f16_ss(dd, dAl + 2 * s, dBh + bo, GEMM_IDESC, 1u);
                }
            }
            TCGEN05_COMMIT(mb[t & 1]);
        }

        if (t + 2 < nst) {
            MBARRIER_WAIT_PARITY(mb[t & 1], (t >> 1) & 1);
            gt_stage(Ah, Al, Bh, Bl, t0 + (t & 1) * GT_STAGE, m0, n0, K,
                     (t + 2) * 64, tid);
        }
    }

    MBARRIER_WAIT_PARITY(mb[(nst - 1) & 1], ((nst - 1) >> 1) & 1);
    TCGEN05_FENCE_AFTER();

    // epilogue: warps 0-3 -> cols 0..127, warps 4-7 -> cols 128..255
    {
        int row = m0 + (wid & 3) * 32 + lane;
        uint32_t cb = (wid >> 2) * 128;
#pragma unroll
        for (int cc = 0; cc < 4; ++cc) {
            uint32_t r[32];
            TCGEN05_LD_X32(r, tmem + cb + cc * 32);
            TCGEN05_WAIT_LD();
            float* dst = &C[(long)row * N + n0 + cb + cc * 32];
#pragma unroll
            for (int q = 0; q < 8; ++q) {
                *(float4*)(dst + q * 4) = make_float4(
                    __uint_as_float(r[q * 4 + 0]), __uint_as_float(r[q * 4 + 1]),
                    __uint_as_float(r[q * 4 + 2]), __uint_as_float(r[q * 4 + 3]));
            }
        }
    }
    __syncthreads();
    if (wid == 0) TCGEN05_DEALLOC(tmem, 256);

#else
    // ============ mma.sync fallback (compiles for plain compute_103;
    //              never selected at runtime when sm_103a cubin exists) =======
    const int wm = (wid >> 1) * 32;       // 4 M-groups
    const int wn = (wid & 1) * 128;       // 2 N-halves of 128

    float acc[2][16][4];
#pragma unroll
    for (int i = 0; i < 2; ++i)
#pragma unroll
        for (int j = 0; j < 16; ++j)
#pragma unroll
            for (int q = 0; q < 4; ++q) acc[i][j][q] = 0.0f;

    for (int t = 0; t < nst; ++t) {
        gt_stage(Ah, Al, Bh, Bl, t0, m0, n0, K, t * 64, tid);
        asm volatile("cp.async.wait_group 0;");
        __syncthreads();

#pragma unroll
        for (int kb = 0; kb < 4; ++kb) {
            uint32_t ah[2][4], al[2][4];
#pragma unroll
            for (int mf = 0; mf < 2; ++mf) {
                int arow = wm + mf * 16 + (lane & 15);
                int col8 = kb * 2 + (lane >> 4);
                uint32_t off = arow * 128 + ((col8 ^ (arow & 7)) << 4);
                ldsm4(ah[mf][0], ah[mf][1], ah[mf][2], ah[mf][3], t0 + off);
                ldsm4(al[mf][0], al[mf][1], al[mf][2], al[mf][3],
                      t0 + GT_ST_A + off);
            }
#pragma unroll
            for (int np = 0; np < 8; ++np) {
                int brow = wn + np * 16 + (lane & 7) + ((lane >> 4) << 3);
                int col8 = kb * 2 + ((lane >> 3) & 1);
                uint32_t off = brow * 128 + ((col8 ^ (brow & 7)) << 4);
                uint32_t bh[4], bl[4];
                ldsm4(bh[0], bh[1], bh[2], bh[3], t0 + 2 * GT_ST_A + off);
                ldsm4(bl[0], bl[1], bl[2], bl[3],
                      t0 + 2 * GT_ST_A + GT_ST_B + off);
#pragma unroll
                for (int hf = 0; hf < 2; ++hf) {
                    int nf = np * 2 + hf;
#pragma unroll
                    for (int mf = 0; mf < 2; ++mf) {
                        mma16816(acc[mf][nf], ah[mf], bh[hf * 2], bh[hf * 2 + 1]);
                        mma16816(acc[mf][nf], ah[mf], bl[hf * 2], bl[hf * 2 + 1]);
                        mma16816(acc[mf][nf], al[mf], bh[hf * 2], bh[hf * 2 + 1]);
                    }
                }
            }
        }
        __syncthreads();
    }

#pragma unroll
    for (int mf = 0; mf < 2; ++mf) {
        int row = m0 + wm + mf * 16 + (lane >> 2);
#pragma unroll
        for (int nf = 0; nf < 16; ++nf) {
            int col = n0 + wn + nf * 8 + (lane & 3) * 2;
            *(float2*)&C[(long)row * N + col] =
                make_float2(acc[mf][nf][0], acc[mf][nf][1]);
            *(float2*)&C[(long)(row + 8) * N + col] =
                make_float2(acc[mf][nf][2], acc[mf][nf][3]);
        }
    }
#endif
}

// ---------------------------------------------------------------------------
// Tensor-core flash attention (mma.sync, causal, GQA 4:1).
// Writes output directly as bf16 hi/lo (feeds O-projection).
// ---------------------------------------------------------------------------
#define ATT_TS (64 * PADK)
#define ATT_SMEM (8 * ATT_TS * 2)

__device__ __forceinline__ void attn_issue(
    const __nv_bfloat16* Kh_, const __nv_bfloat16* Kl_,
    const __nv_bfloat16* Vh_, const __nv_bfloat16* Vl_,
    __nv_bfloat16* sKh, __nv_bfloat16* sKl,
    __nv_bfloat16* sVh, __nv_bfloat16* sVl,
    int j0, int kvh, int tid) {
#pragma unroll
    for (int i = 0; i < 4; ++i) {
        int c = tid + 256 * i;
        int row = c >> 4, c16 = c & 15;
        long g = (long)(j0 + row) * KV_DIM + kvh * HD + c16 * 8;
        int so = row * PADK + c16 * 8;
        cp16(smaddr(sKh + so), Kh_ + g);
        cp16(smaddr(sKl + so), Kl_ + g);
        cp16(smaddr(sVh + so), Vh_ + g);
        cp16(smaddr(sVl + so), Vl_ + g);
    }
    cp_commit();
}

__global__ __launch_bounds__(256, 1)
void attn_mma(const __nv_bfloat16* __restrict__ Qh,
              const __nv_bfloat16* __restrict__ Ql,
              const __nv_bfloat16* __restrict__ Kh_,
              const __nv_bfloat16* __restrict__ Kl_,
              const __nv_bfloat16* __restrict__ Vh_,
              const __nv_bfloat16* __restrict__ Vl_,
              __nv_bfloat16* __restrict__ Oh,
              __nv_bfloat16* __restrict__ Ol) {
    extern __shared__ __nv_bfloat16 sma[];
    __nv_bfloat16* sKh[2] = {sma + 0 * ATT_TS, sma + 1 * ATT_TS};
    __nv_bfloat16* sKl[2] = {sma + 2 * ATT_TS, sma + 3 * ATT_TS};
    __nv_bfloat16* sVh[2] = {sma + 4 * ATT_TS, sma + 5 * ATT_TS};
    __nv_bfloat16* sVl[2] = {sma + 6 * ATT_TS, sma + 7 * ATT_TS};

    const int tid = threadIdx.x;
    const int lane = tid & 31;
    const int w = tid >> 5;
    const int g = lane >> 2;
    const int qq = lane & 3;
    const int h = blockIdx.y;
    const int kvh = h >> 2;
    const int qt = gridDim.x - 1 - blockIdx.x;
    const int q0 = qt * BQT;

    const int r0 = q0 + w * 16 + g;
    const int r1 = r0 + 8;
    uint32_t qfh[8][4], qfl[8][4];
#pragma unroll
    for (int k = 0; k < 8; ++k) {
        int c = h * HD + k * 16 + qq * 2;
        qfh[k][0] = *(const uint32_t*)&Qh[(long)r0 * DIM + c];
        qfh[k][1] = *(const uint32_t*)&Qh[(long)r1 * DIM + c];
        qfh[k][2] = *(const uint32_t*)&Qh[(long)r0 * DIM + c + 8];
        qfh[k][3] = *(const uint32_t*)&Qh[(long)r1 * DIM + c + 8];
        qfl[k][0] = *(const uint32_t*)&Ql[(long)r0 * DIM + c];
        qfl[k][1] = *(const uint32_t*)&Ql[(long)r1 * DIM + c];
        qfl[k][2] = *(const uint32_t*)&Ql[(long)r0 * DIM + c + 8];
        qfl[k][3] = *(const uint32_t*)&Ql[(long)r1 * DIM + c + 8];
    }

    float of[16][4];
#pragma unroll
    for (int i = 0; i < 16; ++i)
#pragma unroll
        for (int j = 0; j < 4; ++j) of[i][j] = 0.0f;
    float m0 = -1e30f, m1 = -1e30f, l0 = 0.0f, l1 = 0.0f;

    const int nt = 2 * qt + 2;
    attn_issue(Kh_, Kl_, Vh_, Vl_, sKh[0], sKl[0], sVh[0], sVl[0], 0, kvh, tid);

    for (int t = 0; t < nt; ++t) {
        if (t + 1 < nt) {
            int bb = (t + 1) & 1;
            attn_issue(Kh_, Kl_, Vh_, Vl_, sKh[bb], sKl[bb], sVh[bb], sVl[bb],
                       (t + 1) * BKT, kvh, tid);
            asm volatile("cp.async.wait_group 1;");
        } else {
            asm volatile("cp.async.wait_group 0;");
        }
        __syncthreads();
        const int buf = t & 1;
        const int j0 = t * BKT;

        float sc[8][4];
#pragma unroll
        for (int i = 0; i < 8; ++i)
#pragma unroll
            for (int j = 0; j < 4; ++j) sc[i][j] = 0.0f;

#pragma unroll
        for (int k = 0; k < 8; ++k) {
#pragma unroll
            for (int np = 0; np < 4; ++np) {
                int brow = np * 16 + (lane & 7) + ((lane >> 4) << 3);
                int bcol = k * 16 + (((lane >> 3) & 1) << 3);
                uint32_t bh[4], bl[4];
                ldsm4(bh[0], bh[1], bh[2], bh[3],
                      smaddr(sKh[buf] + brow * PADK + bcol));
                ldsm4(bl[0], bl[1], bl[2], bl[3],
                      smaddr(sKl[buf] + brow * PADK + bcol));
#pragma unroll
                for (int hf = 0; hf < 2; ++hf) {
                    int nf = np * 2 + hf;
                    mma16816(sc[nf], qfh[k], bh[hf * 2], bh[hf * 2 + 1]);
                    mma16816(sc[nf], qfh[k], bl[hf * 2], bl[hf * 2 + 1]);
                    mma16816(sc[nf], qfl[k], bh[hf * 2], bh[hf * 2 + 1]);
                }
            }
        }

        if (t >= nt - 2) {
#pragma unroll
            for (int nf = 0; nf < 8; ++nf) {
                int cb = j0 + nf * 8 + qq * 2;
                if (cb > r0)     sc[nf][0] = -1e30f;
                if (cb + 1 > r0) sc[nf][1] = -1e30f;
                if (cb > r1)     sc[nf][2] = -1e30f;
                if (cb + 1 > r1) sc[nf][3] = -1e30f;
            }
        }

        float mt0 = -1e30f, mt1 = -1e30f;
#pragma unroll
        for (int nf = 0; nf < 8; ++nf) {
            mt0 = fmaxf(mt0, fmaxf(sc[nf][0], sc[nf][1]));
            mt1 = fmaxf(mt1, fmaxf(sc[nf][2], sc[nf][3]));
        }
        mt0 = fmaxf(mt0, __shfl_xor_sync(0xffffffff, mt0, 1));
        mt0 = fmaxf(mt0, __shfl_xor_sync(0xffffffff, mt0, 2));
        mt1 = fmaxf(mt1, __shfl_xor_sync(0xffffffff, mt1, 1));
        mt1 = fmaxf(mt1, __shfl_xor_sync(0xffffffff, mt1, 2));
        float mn0 = fmaxf(m0, mt0), mn1 = fmaxf(m1, mt1);
        float a0 = __expf(m0 - mn0), a1 = __expf(m1 - mn1);
        m0 = mn0; m1 = mn1;

        float rs0 = 0.0f, rs1 = 0.0f;
#pragma unroll
        for (int nf = 0; nf < 8; ++nf) {
            sc[nf][0] = __expf(sc[nf][0] - mn0); rs0 += sc[nf][0];
            sc[nf][1] = __expf(sc[nf][1] - mn0); rs0 += sc[nf][1];
            sc[nf][2] = __expf(sc[nf][2] - mn1); rs1 += sc[nf][2];
            sc[nf][3] = __expf(sc[nf][3] - mn1); rs1 += sc[nf][3];
        }
        rs0 += __shfl_xor_sync(0xffffffff, rs0, 1);
        rs0 += __shfl_xor_sync(0xffffffff, rs0, 2);
        rs1 += __shfl_xor_sync(0xffffffff, rs1, 1);
        rs1 += __shfl_xor_sync(0xffffffff, rs1, 2);
        l0 = l0 * a0 + rs0;
        l1 = l1 * a1 + rs1;

#pragma unroll
        for (int nf = 0; nf < 16; ++nf) {
            of[nf][0] *= a0; of[nf][1] *= a0;
            of[nf][2] *= a1; of[nf][3] *= a1;
        }

#pragma unroll
        for (int ks = 0; ks < 4; ++ks) {
            uint32_t ph[4], pl[4];
            {
                float s00 = sc[2 * ks][0],     s01 = sc[2 * ks][1];
                float s02 = sc[2 * ks][2],     s03 = sc[2 * ks][3];
                float s10 = sc[2 * ks + 1][0], s11 = sc[2 * ks + 1][1];
                float s12 = sc[2 * ks + 1][2], s13 = sc[2 * ks + 1][3];
                ph[0] = bpack(s00, s01); ph[1] = bpack(s02, s03);
                ph[2] = bpack(s10, s11); ph[3] = bpack(s12, s13);
                __nv_bfloat162* hp;
                hp = (__nv_bfloat162*)&ph[0];
                pl[0] = bpack(s00 - __bfloat162float(hp->x), s01 - __bfloat162float(hp->y));
                hp = (__nv_bfloat162*)&ph[1];
                pl[1] = bpack(s02 - __bfloat162float(hp->x), s03 - __bfloat162float(hp->y));
                hp = (__nv_bfloat162*)&ph[2];
                pl[2] = bpack(s10 - __bfloat162float(hp->x), s11 - __bfloat162float(hp->y));
                hp = (__nv_bfloat162*)&ph[3];
                pl[3] = bpack(s12 - __bfloat162float(hp->x), s13 - __bfloat162float(hp->y));
            }
            int vrow = ks * 16 + (lane & 7) + (((lane >> 3) & 1) << 3);
#pragma unroll
            for (int nn = 0; nn < 8; ++nn) {
                int vcol = nn * 16 + ((lane >> 4) << 3);
                uint32_t vh[4], vl[4];
                ldsm4t(vh[0], vh[1], vh[2], vh[3],
                       smaddr(sVh[buf] + vrow * PADK + vcol));
                ldsm4t(vl[0], vl[1], vl[2], vl[3],
                       smaddr(sVl[buf] + vrow * PADK + vcol));
                mma16816(of[nn * 2], ph, vh[0], vh[1]);
                mma16816(of[nn * 2], ph, vl[0], vl[1]);
                mma16816(of[nn * 2], pl, vh[0], vh[1]);
                mma16816(of[nn * 2 + 1], ph, vh[2], vh[3]);
                mma16816(of[nn * 2 + 1], ph, vl[2], vl[3]);
                mma16816(of[nn * 2 + 1], pl, vh[2], vh[3]);
            }
        }
        __syncthreads();
    }

    // normalize + store as bf16 hi/lo (input to O-projection)
    float inv0 = 1.0f / l0, inv1 = 1.0f / l1;
#pragma unroll
    for (int nf = 0; nf < 16; ++nf) {
        int col = h * HD + nf * 8 + qq * 2;
        {
            float a = of[nf][0] * inv0, b = of[nf][1] * inv0;
            uint32_t hh = bpack(a, b);
            __nv_bfloat162 hv = *(__nv_bfloat162*)&hh;
            uint32_t ll = bpack(a - __bfloat162float(hv.x),
                                b - __bfloat162float(hv.y));
            *(uint32_t*)&Oh[(long)r0 * DIM + col] = hh;
            *(uint32_t*)&Ol[(long)r0 * DIM + col] = ll;
        }
        {
            float a = of[nf][2] * inv1, b = of[nf][3] * inv1;
            uint32_t hh = bpack(a, b);
            __nv_bfloat162 hv = *(__nv_bfloat162*)&hh;
            uint32_t ll = bpack(a - __bfloat162float(hv.x),
                                b - __bfloat162float(hv.y));
            *(uint32_t*)&Oh[(long)r1 * DIM + col] = hh;
            *(uint32_t*)&Ol[(long)r1 * DIM + col] = ll;
        }
    }
}

// ---------------------------------------------------------------------------
// Launcher
// ---------------------------------------------------------------------------
extern "C" void kernel_launch(void* const* d_in, const int* in_sizes, int n_in,
                              void* d_out, int out_size) {
    const float* x  = (const float*)d_in[0];
    const float* wq = (const float*)d_in[1];
    const float* wk = (const float*)d_in[2];
    const float* wv = (const float*)d_in[3];
    const float* wo = (const float*)d_in[4];
    const float* fc = (const float*)d_in[5];
    const float* fs = (const float*)d_in[6];
    float* out = (float*)d_out;

    float *Qp, *Kp, *Vp;
    cudaGetSymbolAddress((void**)&Qp, g_Q);
    cudaGetSymbolAddress((void**)&Kp, g_K);
    cudaGetSymbolAddress((void**)&Vp, g_V);

    __nv_bfloat16 *xh, *xl, *wqh, *wql, *wkh, *wkl, *wvh, *wvl, *woh, *wol, *oh, *ol;
    __nv_bfloat16 *qh, *ql, *kh, *kl, *vh, *vl;
    cudaGetSymbolAddress((void**)&xh,  g_xh);  cudaGetSymbolAddress((void**)&xl,  g_xl);
    cudaGetSymbolAddress((void**)&wqh, g_wqh); cudaGetSymbolAddress((void**)&wql, g_wql);
    cudaGetSymbolAddress((void**)&wkh, g_wkh); cudaGetSymbolAddress((void**)&wkl, g_wkl);
    cudaGetSymbolAddress((void**)&wvh, g_wvh); cudaGetSymbolAddress((void**)&wvl, g_wvl);
    cudaGetSymbolAddress((void**)&woh, g_woh); cudaGetSymbolAddress((void**)&wol, g_wol);
    cudaGetSymbolAddress((void**)&oh,  g_oh);  cudaGetSymbolAddress((void**)&ol,  g_ol);
    cudaGetSymbolAddress((void**)&qh,  g_Qh);  cudaGetSymbolAddress((void**)&ql,  g_Ql);
    cudaGetSymbolAddress((void**)&kh,  g_Kh);  cudaGetSymbolAddress((void**)&kl,  g_Kl);
    cudaGetSymbolAddress((void**)&vh,  g_Vh);  cudaGetSymbolAddress((void**)&vl,  g_Vl);

    cudaFuncSetAttribute(gemm_tc,
                         cudaFuncAttributeMaxDynamicSharedMemorySize, GT_SMEM);
    cudaFuncSetAttribute(attn_mma,
                         cudaFuncAttributeMaxDynamicSharedMemorySize, ATT_SMEM);

    auto launch_split = [](const float* in, __nv_bfloat16* hi, __nv_bfloat16* lo, int n) {
        int n4 = n / 4;
        split_bf16<<<(n4 + 255) / 256, 256>>>(in, hi, lo, n4);
    };
    launch_split(x,  xh,  xl,  SEQ * DIM);
    launch_split(wq, wqh, wql, DIM * DIM);
    launch_split(wk, wkh, wkl, KV_DIM * DIM);
    launch_split(wv, wvh, wvl, KV_DIM * DIM);
    launch_split(wo, woh, wol, DIM * DIM);

    // Q projection (128x256 tiles)
    gemm_tc<<<dim3(DIM / 256, SEQ / 128), 256, GT_SMEM>>>(
        xh, xl, wqh, wql, Qp, nullptr, nullptr, nullptr, SEQ, DIM, DIM);
    // K+V projections fused into one launch (dual-B)
    gemm_tc<<<dim3(2 * KV_DIM / 256, SEQ / 128), 256, GT_SMEM>>>(
        xh, xl, wkh, wkl, Kp, wvh, wvl, Vp, SEQ, KV_DIM, DIM);

    // RoPE + split (Q pre-scaled); V split
    int qpairs = SEQ * NH * (HD / 2);
    int kpairs = SEQ * NKV * (HD / 2);
    rope_split<<<(qpairs + 255) / 256, 256>>>(Qp, qh, ql, fc, fs, NH, 0.08838834764831845f);
    rope_split<<<(kpairs + 255) / 256, 256>>>(Kp, kh, kl, fc, fs, NKV, 1.0f);
    launch_split(Vp, vh, vl, SEQ * KV_DIM);

    // Flash attention -> bf16 hi/lo output
    attn_mma<<<dim3(SEQ / BQT, NH), 256, ATT_SMEM>>>(qh, ql, kh, kl, vh, vl, oh, ol);

    // Output projection
    gemm_tc<<<dim3(DIM / 256, SEQ / 128), 256, GT_SMEM>>>(
        oh, ol, woh, wol, out, nullptr, nullptr, nullptr, SEQ, DIM, DIM);
}

// round 7
// speedup vs baseline: 7.6997x; 1.1576x over previous
#include <cuda_runtime.h>
#include <cuda_bf16.h>
#include <stdint.h>

#define SEQ    2048
#define DIM    4096
#define NH     32
#define NKV    8
#define HD     128
#define KV_DIM 1024
#define BQT    128
#define BKT    64
#define PADK   136

#if defined(__CUDA_ARCH_FEAT_SM103_ALL) || defined(__CUDA_ARCH_FEAT_SM100_ALL)
#define HAS_TCGEN05 1
#else
#define HAS_TCGEN05 0
#endif

// ---------------------------------------------------------------------------
// Static device scratch
// ---------------------------------------------------------------------------
__device__ float g_Q[SEQ * DIM];
__device__ float g_K[SEQ * KV_DIM];
__device__ float g_V[SEQ * KV_DIM];

__device__ __nv_bfloat16 g_xh[SEQ * DIM],     g_xl[SEQ * DIM];
__device__ __nv_bfloat16 g_wqh[DIM * DIM],    g_wql[DIM * DIM];
__device__ __nv_bfloat16 g_wkh[KV_DIM * DIM], g_wkl[KV_DIM * DIM];
__device__ __nv_bfloat16 g_wvh[KV_DIM * DIM], g_wvl[KV_DIM * DIM];
__device__ __nv_bfloat16 g_woh[DIM * DIM],    g_wol[DIM * DIM];
__device__ __nv_bfloat16 g_oh[SEQ * DIM],     g_ol[SEQ * DIM];

__device__ __nv_bfloat16 g_Qh[SEQ * DIM],     g_Ql[SEQ * DIM];
__device__ __nv_bfloat16 g_Kh[SEQ * KV_DIM],  g_Kl[SEQ * KV_DIM];
__device__ __nv_bfloat16 g_Vh[SEQ * KV_DIM],  g_Vl[SEQ * KV_DIM];
__device__ __nv_bfloat16 g_Vth[KV_DIM * SEQ], g_Vtl[KV_DIM * SEQ];  // [d][seq]

// ---------------------------------------------------------------------------
// Helpers
// ---------------------------------------------------------------------------
__device__ __forceinline__ uint32_t smaddr(const void* p) {
    return (uint32_t)__cvta_generic_to_shared(p);
}
__device__ __forceinline__ void cp16(uint32_t s, const void* g) {
    asm volatile("cp.async.cg.shared.global [%0], [%1], 16;" :: "r"(s), "l"(g));
}
__device__ __forceinline__ void cp_commit() {
    asm volatile("cp.async.commit_group;");
}
__device__ __forceinline__ void ldsm4(uint32_t& r0, uint32_t& r1,
                                      uint32_t& r2, uint32_t& r3, uint32_t a) {
    asm volatile("ldmatrix.sync.aligned.m8n8.x4.shared.b16 {%0,%1,%2,%3}, [%4];"
                 : "=r"(r0), "=r"(r1), "=r"(r2), "=r"(r3) : "r"(a));
}
__device__ __forceinline__ void ldsm4t(uint32_t& r0, uint32_t& r1,
                                       uint32_t& r2, uint32_t& r3, uint32_t a) {
    asm volatile("ldmatrix.sync.aligned.m8n8.x4.trans.shared.b16 {%0,%1,%2,%3}, [%4];"
                 : "=r"(r0), "=r"(r1), "=r"(r2), "=r"(r3) : "r"(a));
}
__device__ __forceinline__ void mma16816(float* c, const uint32_t* a,
                                         uint32_t b0, uint32_t b1) {
    asm volatile(
        "mma.sync.aligned.m16n8k16.row.col.f32.bf16.bf16.f32 "
        "{%0,%1,%2,%3},{%4,%5,%6,%7},{%8,%9},{%0,%1,%2,%3};"
        : "+f"(c[0]), "+f"(c[1]), "+f"(c[2]), "+f"(c[3])
        : "r"(a[0]), "r"(a[1]), "r"(a[2]), "r"(a[3]), "r"(b0), "r"(b1));
}
__device__ __forceinline__ uint32_t bpack(float a, float b) {
    __nv_bfloat162 v;
    v.x = __float2bfloat16(a);
    v.y = __float2bfloat16(b);
    return *(uint32_t*)&v;
}

// ---- tcgen05 -----------------------------------------------------------------
static constexpr uint64_t SMEM_DESC_BASE_SW128 =
    (uint64_t(2)  << 61) | (uint64_t(1) << 46) |
    (uint64_t(64) << 32) | (uint64_t(1) << 16);
#define MAKE_SMEM_DESC(base_addr) \
    (SMEM_DESC_BASE_SW128 | ((uint64_t)((base_addr) >> 4) & 0x3FFF))

#define MBARRIER_INIT(mbar, count) \
    asm volatile("mbarrier.init.shared.b64 [%0], %1;" \
                 :: "r"((uint32_t)(mbar)), "r"((uint32_t)(count)) : "memory")
#define FENCE_ASYNC() \
    asm volatile("fence.proxy.async.shared::cta;" ::: "memory")

#define MBARRIER_WAIT_PARITY(mbar_smem_addr, phase_parity) do { \
    uint32_t _mbar = (uint32_t)(mbar_smem_addr); \
    uint32_t _parity = (uint32_t)(phase_parity); \
    uint32_t _done; \
    asm volatile( \
        "{\n\t.reg .pred p;\n\t" \
        "mbarrier.try_wait.parity.acquire.cta.shared::cta.b64 p, [%1], %2;\n\t" \
        "selp.b32 %0, 1, 0, p;\n\t}" \
        : "=r"(_done) : "r"(_mbar), "r"(_parity) : "memory"); \
    if (!_done) { \
        asm volatile( \
            "{\n\t.reg .pred P1;\n\t" \
            "WAIT_LOOP_%=:\n\t" \
            "mbarrier.try_wait.parity.acquire.cta.shared::cta.b64 P1, [%0], %1, 0x989680;\n\t" \
            "@P1 bra.uni WAIT_DONE_%=;\n\t" \
            "bra.uni WAIT_LOOP_%=;\n\t" \
            "WAIT_DONE_%=:\n\t}" \
            :: "r"(_mbar), "r"(_parity) : "memory"); \
    } \
} while(0)

#if HAS_TCGEN05
#define TCGEN05_ALLOC(smem_result_addr, nCols) \
    asm volatile("tcgen05.alloc.cta_group::1.sync.aligned.shared::cta.b32 [%0], %1;" \
                 :: "r"((uint32_t)(smem_result_addr)), "r"((uint32_t)(nCols)) : "memory")
#define TCGEN05_DEALLOC(tmem_addr, nCols) \
    asm volatile("tcgen05.dealloc.cta_group::1.sync.aligned.b32 %0, %1;" \
                 :: "r"(tmem_addr), "r"((uint32_t)(nCols)))
#define TCGEN05_RELINQ() \
    asm volatile("tcgen05.relinquish_alloc_permit.cta_group::1.sync.aligned;")
#define TCGEN05_COMMIT(mbar) \
    asm volatile("tcgen05.commit.cta_group::1.mbarrier::arrive::one.shared::cluster.b64 [%0];" \
                 :: "r"((uint32_t)(mbar)) : "memory")
#define TCGEN05_FENCE_AFTER() \
    asm volatile("tcgen05.fence::after_thread_sync;" ::: "memory")
#define TCGEN05_FENCE_BEFORE() \
    asm volatile("tcgen05.fence::before_thread_sync;" ::: "memory")
#define TCGEN05_WAIT_LD() \
    asm volatile("tcgen05.wait::ld.sync.aligned;" ::: "memory")
#define TCGEN05_WAIT_ST() \
    asm volatile("tcgen05.wait::st.sync.aligned;" ::: "memory")
#define TCGEN05_LD_X32(r, tmem_addr) \
    asm volatile( \
        "tcgen05.ld.sync.aligned.32x32b.x32.b32 " \
        "{%0, %1, %2, %3, %4, %5, %6, %7, " \
        " %8, %9, %10, %11, %12, %13, %14, %15, " \
        " %16, %17, %18, %19, %20, %21, %22, %23, " \
        " %24, %25, %26, %27, %28, %29, %30, %31}, [%32];" \
        : "=r"((r)[0]),  "=r"((r)[1]),  "=r"((r)[2]),  "=r"((r)[3]), \
          "=r"((r)[4]),  "=r"((r)[5]),  "=r"((r)[6]),  "=r"((r)[7]), \
          "=r"((r)[8]),  "=r"((r)[9]),  "=r"((r)[10]), "=r"((r)[11]), \
          "=r"((r)[12]), "=r"((r)[13]), "=r"((r)[14]), "=r"((r)[15]), \
          "=r"((r)[16]), "=r"((r)[17]), "=r"((r)[18]), "=r"((r)[19]), \
          "=r"((r)[20]), "=r"((r)[21]), "=r"((r)[22]), "=r"((r)[23]), \
          "=r"((r)[24]), "=r"((r)[25]), "=r"((r)[26]), "=r"((r)[27]), \
          "=r"((r)[28]), "=r"((r)[29]), "=r"((r)[30]), "=r"((r)[31]) \
        : "r"(tmem_addr))
#define TCGEN05_ST_X16(tmem_addr, r) \
    asm volatile( \
        "tcgen05.st.sync.aligned.32x32b.x16.b32 [%0], " \
        "{%1, %2, %3, %4, %5, %6, %7, %8, " \
        " %9, %10, %11, %12, %13, %14, %15, %16};" \
        :: "r"(tmem_addr), \
           "r"((r)[0]),  "r"((r)[1]),  "r"((r)[2]),  "r"((r)[3]), \
           "r"((r)[4]),  "r"((r)[5]),  "r"((r)[6]),  "r"((r)[7]), \
           "r"((r)[8]),  "r"((r)[9]),  "r"((r)[10]), "r"((r)[11]), \
           "r"((r)[12]), "r"((r)[13]), "r"((r)[14]), "r"((r)[15]) \
        : "memory")

__device__ __forceinline__ void umma_f16_ss(uint32_t d, uint64_t a, uint64_t b,
                                            uint32_t idesc, uint32_t en) {
    asm volatile(
        "{\n\t.reg .pred p;\n\t"
        "setp.ne.u32 p, %5, 0;\n\t"
        "tcgen05.mma.cta_group::1.kind::f16 [%0], %1, %2, %3, {%4,%4,%4,%4}, p;\n\t}"
        :: "r"(d), "l"(a), "l"(b), "r"(idesc), "r"(0u), "r"(en) : "memory");
}
__device__ __forceinline__ void umma_f16_ts(uint32_t d, uint32_t a_tmem,
                                            uint64_t b, uint32_t idesc,
                                            uint32_t en) {
    asm volatile(
        "{\n\t.reg .pred p;\n\t"
        "setp.ne.u32 p, %5, 0;\n\t"
        "tcgen05.mma.cta_group::1.kind::f16 [%0], [%1], %2, %3, {%4,%4,%4,%4}, p;\n\t}"
        :: "r"(d), "r"(a_tmem), "l"(b), "r"(idesc), "r"(0u), "r"(en) : "memory");
}
#endif

// idescs: F32 accum, bf16 A/B, M=128; N variants
#define GEMM_IDESC ((1u<<4)|(1u<<7)|(1u<<10)|((128u/8)<<17)|((128u/16)<<24))
#define IDESC_S    ((1u<<4)|(1u<<7)|(1u<<10)|((64u/8)<<17)|((128u/16)<<24))
#define IDESC_PV   GEMM_IDESC

// ---------------------------------------------------------------------------
// fp32 -> bf16 hi/lo split
// ---------------------------------------------------------------------------
__global__ void split_bf16(const float* __restrict__ in,
                           __nv_bfloat16* __restrict__ hi,
                           __nv_bfloat16* __restrict__ lo, int n4) {
    int i = blockIdx.x * blockDim.x + threadIdx.x;
    if (i >= n4) return;
    float4 v = ((const float4*)in)[i];
    __nv_bfloat16 h0 = __float2bfloat16(v.x);
    __nv_bfloat16 h1 = __float2bfloat16(v.y);
    __nv_bfloat16 h2 = __float2bfloat16(v.z);
    __nv_bfloat16 h3 = __float2bfloat16(v.w);
    __nv_bfloat162* hp = (__nv_bfloat162*)hi;
    __nv_bfloat162* lp = (__nv_bfloat162*)lo;
    hp[i * 2 + 0] = __halves2bfloat162(h0, h1);
    hp[i * 2 + 1] = __halves2bfloat162(h2, h3);
    lp[i * 2 + 0] = __halves2bfloat162(
        __float2bfloat16(v.x - __bfloat162float(h0)),
        __float2bfloat16(v.y - __bfloat162float(h1)));
    lp[i * 2 + 1] = __halves2bfloat162(
        __float2bfloat16(v.z - __bfloat162float(h2)),
        __float2bfloat16(v.w - __bfloat162float(h3)));
}

// ---------------------------------------------------------------------------
// RoPE + scale + hi/lo split
// ---------------------------------------------------------------------------
__global__ void rope_split(const float* __restrict__ X,
                           __nv_bfloat16* __restrict__ Xh,
                           __nv_bfloat16* __restrict__ Xl,
                           const float* __restrict__ cs,
                           const float* __restrict__ sn,
                           int nheads, float scale) {
    int pps = nheads * (HD / 2);
    int total = SEQ * pps;
    int idx = blockIdx.x * blockDim.x + threadIdx.x;
    if (idx >= total) return;
    int s = idx / pps;
    int r = idx - s * pps;
    int p = r & 63;
    float2 v = ((const float2*)X)[idx];
    float c = cs[s * 64 + p], si = sn[s * 64 + p];
    float o0 = (v.x * c - v.y * si) * scale;
    float o1 = (v.x * si + v.y * c) * scale;
    __nv_bfloat16 h0 = __float2bfloat16(o0);
    __nv_bfloat16 h1 = __float2bfloat16(o1);
    ((__nv_bfloat162*)Xh)[idx] = __halves2bfloat162(h0, h1);
    ((__nv_bfloat162*)Xl)[idx] = __halves2bfloat162(
        __float2bfloat16(o0 - __bfloat162float(h0)),
        __float2bfloat16(o1 - __bfloat162float(h1)));
}

// ---------------------------------------------------------------------------
// V transpose + split: V[seq][KV_DIM] fp32 -> Vt[d][seq] bf16 hi/lo
// ---------------------------------------------------------------------------
__global__ void vt_split(const float* __restrict__ V,
                         __nv_bfloat16* __restrict__ Vth,
                         __nv_bfloat16* __restrict__ Vtl) {
    __shared__ float tile[32][33];
    int s0 = blockIdx.x * 32, d0 = blockIdx.y * 32;
    int tx = threadIdx.x;
    for (int r = threadIdx.y; r < 32; r += 8)
        tile[r][tx] = V[(long)(s0 + r) * KV_DIM + d0 + tx];
    __syncthreads();
    for (int r = threadIdx.y; r < 32; r += 8) {
        float v = tile[tx][r];
        __nv_bfloat16 h = __float2bfloat16(v);
        long o = (long)(d0 + r) * SEQ + s0 + tx;
        Vth[o] = h;
        Vtl[o] = __float2bfloat16(v - __bfloat162float(h));
    }
}

// ---------------------------------------------------------------------------
// Dual-path GEMM (NT), unchanged from R6 (proven): 128x256 tile, tcgen05.
// ---------------------------------------------------------------------------
#define GT_ST_A 16384
#define GT_ST_B 32768
#define GT_STAGE (2*GT_ST_A + 2*GT_ST_B)
#define GT_SMEM (1024 + 2*GT_STAGE + 64)

__device__ __forceinline__ void gt_stage(
    const __nv_bfloat16* Ah, const __nv_bfloat16* Al,
    const __nv_bfloat16* Bh, const __nv_bfloat16* Bl,
    uint32_t sb, int m0, int n0, int K, int kc, int tid) {
#pragma unroll
    for (int i = 0; i < 4; ++i) {
        int c = tid + 256 * i;
        int row = c >> 3, col = c & 7;
        int so = row * 128 + ((col ^ (row & 7)) << 4);
        long ga = (long)(m0 + row) * K + kc + col * 8;
        cp16(sb + so,           Ah + ga);
        cp16(sb + GT_ST_A + so, Al + ga);
    }
#pragma unroll
    for (int i = 0; i < 8; ++i) {
        int c = tid + 256 * i;
        int row = c >> 3, col = c & 7;
        int so = row * 128 + ((col ^ (row & 7)) << 4);
        long gb = (long)(n0 + row) * K + kc + col * 8;
        cp16(sb + 2 * GT_ST_A + so,            Bh + gb);
        cp16(sb + 2 * GT_ST_A + GT_ST_B + so,  Bl + gb);
    }
    cp_commit();
}

__global__ __launch_bounds__(256, 1)
void gemm_tc(const __nv_bfloat16* __restrict__ Ah,
             const __nv_bfloat16* __restrict__ Al,
             const __nv_bfloat16* __restrict__ Bh_,
             const __nv_bfloat16* __restrict__ Bl_,
             float* __restrict__ C_,
             const __nv_bfloat16* __restrict__ Bh2,
             const __nv_bfloat16* __restrict__ Bl2,
             float* __restrict__ C2,
             int M, int N, int K) {
    extern __shared__ char smg_raw[];
    uint32_t u = smaddr(smg_raw);
    uint32_t t0 = (u + 1023u) & ~1023u;
    const int tid = threadIdx.x;
    const int wid = tid >> 5;
    const int lane = tid & 31;
    const int m0 = blockIdx.y * 128;
    const int nst = K >> 6;

    const __nv_bfloat16* Bh = Bh_;
    const __nv_bfloat16* Bl = Bl_;
    float* C = C_;
    int bx = blockIdx.x;
    if (C2 != nullptr) {
        int half = gridDim.x >> 1;
        if (bx >= half) { bx -= half; Bh = Bh2; Bl = Bl2; C = C2; }
    }
    const int n0 = bx * 256;

#if HAS_TCGEN05
    uint32_t ctrl = t0 + 2 * GT_STAGE;
    uint32_t mb[2] = {ctrl + 8, ctrl + 16};

    if (wid == 0) {
        TCGEN05_ALLOC(ctrl, 256);
        TCGEN05_RELINQ();
    }
    if (tid == 0) {
        MBARRIER_INIT(mb[0], 1);
        MBARRIER_INIT(mb[1], 1);
    }
    __syncthreads();
    uint32_t tmem;
    asm volatile("ld.shared.b32 %0, [%1];" : "=r"(tmem) : "r"(ctrl));

    gt_stage(Ah, Al, Bh, Bl, t0,            m0, n0, K, 0,  tid);
    gt_stage(Ah, Al, Bh, Bl, t0 + GT_STAGE, m0, n0, K, 64, tid);

    for (int t = 0; t < nst; ++t) {
        if (t + 1 < nst) asm volatile("cp.async.wait_group 1;");
        else             asm volatile("cp.async.wait_group 0;");
        FENCE_ASYNC();
        __syncthreads();

        if (tid == 0) {
            TCGEN05_FENCE_AFTER();
            uint32_t base = t0 + (t & 1) * GT_STAGE;
            uint64_t dAh = MAKE_SMEM_DESC(base);
            uint64_t dAl = MAKE_SMEM_DESC(base + GT_ST_A);
            uint64_t dBh = MAKE_SMEM_DESC(base + 2 * GT_ST_A);
            uint64_t dBl = MAKE_SMEM_DESC(base + 2 * GT_ST_A + GT_ST_B);
#pragma unroll
            for (int s = 0; s < 4; ++s) {
#pragma unroll
                for (int nh = 0; nh < 2; ++nh) {
                    uint64_t bo = (uint64_t)(2 * s + nh * 1024);
                    uint32_t dd = tmem + nh * 128;
                    umma_f16_ss(dd, dAh + 2 * s, dBh + bo, GEMM_IDESC,
                                (t == 0 && s == 0) ? 0u : 1u);
                    umma_f16_ss(dd, dAh + 2 * s, dBl + bo, GEMM_IDESC, 1u);
                    umma_f16_ss(dd, dAl + 2 * s, dBh + bo, GEMM_IDESC, 1u);
                }
            }
            TCGEN05_COMMIT(mb[t & 1]);
        }

        if (t + 2 < nst) {
            MBARRIER_WAIT_PARITY(mb[t & 1], (t >> 1) & 1);
            gt_stage(Ah, Al, Bh, Bl, t0 + (t & 1) * GT_STAGE, m0, n0, K,
                     (t + 2) * 64, tid);
        }
    }

    MBARRIER_WAIT_PARITY(mb[(nst - 1) & 1], ((nst - 1) >> 1) & 1);
    TCGEN05_FENCE_AFTER();

    {
        int row = m0 + (wid & 3) * 32 + lane;
        uint32_t cb = (wid >> 2) * 128;
#pragma unroll
        for (int cc = 0; cc < 4; ++cc) {
            uint32_t r[32];
            TCGEN05_LD_X32(r, tmem + cb + cc * 32);
            TCGEN05_WAIT_LD();
            float* dst = &C[(long)row * N + n0 + cb + cc * 32];
#pragma unroll
            for (int q = 0; q < 8; ++q) {
                *(float4*)(dst + q * 4) = make_float4(
                    __uint_as_float(r[q * 4 + 0]), __uint_as_float(r[q * 4 + 1]),
                    __uint_as_float(r[q * 4 + 2]), __uint_as_float(r[q * 4 + 3]));
            }
        }
    }
    __syncthreads();
    if (wid == 0) TCGEN05_DEALLOC(tmem, 256);

#else
    const int wm = (wid >> 1) * 32;
    const int wn = (wid & 1) * 128;

    float acc[2][16][4];
#pragma unroll
    for (int i = 0; i < 2; ++i)
#pragma unroll
        for (int j = 0; j < 16; ++j)
#pragma unroll
            for (int q = 0; q < 4; ++q) acc[i][j][q] = 0.0f;

    for (int t = 0; t < nst; ++t) {
        gt_stage(Ah, Al, Bh, Bl, t0, m0, n0, K, t * 64, tid);
        asm volatile("cp.async.wait_group 0;");
        __syncthreads();

#pragma unroll
        for (int kb = 0; kb < 4; ++kb) {
            uint32_t ah[2][4], al[2][4];
#pragma unroll
            for (int mf = 0; mf < 2; ++mf) {
                int arow = wm + mf * 16 + (lane & 15);
                int col8 = kb * 2 + (lane >> 4);
                uint32_t off = arow * 128 + ((col8 ^ (arow & 7)) << 4);
                ldsm4(ah[mf][0], ah[mf][1], ah[mf][2], ah[mf][3], t0 + off);
                ldsm4(al[mf][0], al[mf][1], al[mf][2], al[mf][3],
                      t0 + GT_ST_A + off);
            }
#pragma unroll
            for (int np = 0; np < 8; ++np) {
                int brow = wn + np * 16 + (lane & 7) + ((lane >> 4) << 3);
                int col8 = kb * 2 + ((lane >> 3) & 1);
                uint32_t off = brow * 128 + ((col8 ^ (brow & 7)) << 4);
                uint32_t bh[4], bl[4];
                ldsm4(bh[0], bh[1], bh[2], bh[3], t0 + 2 * GT_ST_A + off);
                ldsm4(bl[0], bl[1], bl[2], bl[3],
                      t0 + 2 * GT_ST_A + GT_ST_B + off);
#pragma unroll
                for (int hf = 0; hf < 2; ++hf) {
                    int nf = np * 2 + hf;
#pragma unroll
                    for (int mf = 0; mf < 2; ++mf) {
                        mma16816(acc[mf][nf], ah[mf], bh[hf * 2], bh[hf * 2 + 1]);
                        mma16816(acc[mf][nf], ah[mf], bl[hf * 2], bl[hf * 2 + 1]);
                        mma16816(acc[mf][nf], al[mf], bh[hf * 2], bh[hf * 2 + 1]);
                    }
                }
            }
        }
        __syncthreads();
    }

#pragma unroll
    for (int mf = 0; mf < 2; ++mf) {
        int row = m0 + wm + mf * 16 + (lane >> 2);
#pragma unroll
        for (int nf = 0; nf < 16; ++nf) {
            int col = n0 + wn + nf * 8 + (lane & 3) * 2;
            *(float2*)&C[(long)row * N + col] =
                make_float2(acc[mf][nf][0], acc[mf][nf][1]);
            *(float2*)&C[(long)(row + 8) * N + col] =
                make_float2(acc[mf][nf][2], acc[mf][nf][3]);
        }
    }
#endif
}

// ---------------------------------------------------------------------------
// tcgen05 flash attention (causal, GQA 4:1); mma.sync fallback under #else.
// CTA = (head, 128-query tile), 256 threads (8 warps).
// smem: Q 64KB + 2 stages x 64KB (Kh/Kl chunks + Vth/Vtl) + ctrl + reduce.
// TMEM: S [0,64) | Ph [64,96) | Pl [96,128) | PV [128,256).
// ---------------------------------------------------------------------------
#define ATC_STAGE 65536
#define ATC_CTRL  (3 * 65536)
#define ATC_SMEM  (1024 + ATC_CTRL + 64 + 3072)
#define ATT_TS (64 * PADK)
#define ATT_SMEM_FB (8 * ATT_TS * 2)

__device__ __forceinline__ void atc_stage(
    const __nv_bfloat16* Kh, const __nv_bfloat16* Kl,
    const __nv_bfloat16* Vth, const __nv_bfloat16* Vtl,
    uint32_t sbase, int j0, int kvh, int tid) {
#pragma unroll
    for (int i = 0; i < 4; ++i) {          // K tile: 64 rows x 256B (2 chunks)
        int c = tid + 256 * i;             // 0..1023
        int kr = c >> 4, kc = c & 15;
        int ch = kc >> 3, col = kc & 7;
        uint32_t so = sbase + ch * 8192 + kr * 128 + ((col ^ (kr & 7)) << 4);
        long g = (long)(j0 + kr) * KV_DIM + kvh * HD + kc * 8;
        cp16(so,          Kh + g);
        cp16(so + 16384,  Kl + g);
    }
#pragma unroll
    for (int i = 0; i < 4; ++i) {          // Vt tile: 128 rows x 128B
        int c = tid + 256 * i;
        int vr = c >> 3, col = c & 7;
        uint32_t so = sbase + 32768 + vr * 128 + ((col ^ (vr & 7)) << 4);
        long g = (long)(kvh * HD + vr) * SEQ + j0 + col * 8;
        cp16(so,          Vth + g);
        cp16(so + 16384,  Vtl + g);
    }
    cp_commit();
}

__device__ __forceinline__ void attn_issue_fb(
    const __nv_bfloat16* Kh_, const __nv_bfloat16* Kl_,
    const __nv_bfloat16* Vh_, const __nv_bfloat16* Vl_,
    __nv_bfloat16* sKh, __nv_bfloat16* sKl,
    __nv_bfloat16* sVh, __nv_bfloat16* sVl,
    int j0, int kvh, int tid) {
#pragma unroll
    for (int i = 0; i < 4; ++i) {
        int c = tid + 256 * i;
        int row = c >> 4, c16 = c & 15;
        long g = (long)(j0 + row) * KV_DIM + kvh * HD + c16 * 8;
        int so = row * PADK + c16 * 8;
        cp16(smaddr(sKh + so), Kh_ + g);
        cp16(smaddr(sKl + so), Kl_ + g);
        cp16(smaddr(sVh + so), Vh_ + g);
        cp16(smaddr(sVl + so), Vl_ + g);
    }
    cp_commit();
}

__global__ __launch_bounds__(256, 1)
void attn_tc(const __nv_bfloat16* __restrict__ Qh,
             const __nv_bfloat16* __restrict__ Ql,
             const __nv_bfloat16* __restrict__ Kh,
             const __nv_bfloat16* __restrict__ Kl,
             const __nv_bfloat16* __restrict__ Vh,
             const __nv_bfloat16* __restrict__ Vl,
             const __nv_bfloat16* __restrict__ Vth,
             const __nv_bfloat16* __restrict__ Vtl,
             __nv_bfloat16* __restrict__ Oh,
             __nv_bfloat16* __restrict__ Ol) {
    extern __shared__ char smg_raw[];
    const int tid = threadIdx.x;
    const int lane = tid & 31;
    const int w = tid >> 5;
    const int h = blockIdx.y;
    const int kvh = h >> 2;
    const int qt = gridDim.x - 1 - blockIdx.x;
    const int q0 = qt * BQT;
    const int nt = 2 * qt + 2;

#if HAS_TCGEN05
    uint32_t u = smaddr(smg_raw);
    uint32_t t0 = (u + 1023u) & ~1023u;
    char* gb = smg_raw + (t0 - u);
    const int half = w >> 2;               // column half
    const int sp = w & 3;                  // subpartition
    const int row = sp * 32 + lane;        // 0..127 within q tile
    const int qrow = q0 + row;

    uint32_t ctrl = t0 + ATC_CTRL;
    uint32_t mbs = ctrl + 8, mbpv = ctrl + 16;
    float* red0 = (float*)(gb + ATC_CTRL + 64);    // max  [2][128]
    float* red1 = red0 + 256;                      // sum  [2][128]
    float* smm  = red1 + 256;                      // m    [128]
    float* sml  = smm + 128;                       // l    [128]

    if (w == 0) {
        TCGEN05_ALLOC(ctrl, 256);
        TCGEN05_RELINQ();
    }
    if (tid == 0) {
        MBARRIER_INIT(mbs, 1);
        MBARRIER_INIT(mbpv, 1);
    }
    if (tid < 128) { smm[tid] = -1e30f; sml[tid] = 0.0f; }
    __syncthreads();
    uint32_t tmem;
    asm volatile("ld.shared.b32 %0, [%1];" : "=r"(tmem) : "r"(ctrl));

    // Q load (stays whole kernel): 2 chunks x [128][128B], hi at t0, lo +32KB
#pragma unroll
    for (int i = 0; i < 8; ++i) {
        int c = tid + 256 * i;             // 0..2047
        int r = c >> 4, kc = c & 15;
        int ch = kc >> 3, col = kc & 7;
        uint32_t so = t0 + ch * 16384 + r * 128 + ((col ^ (r & 7)) << 4);
        long g = (long)(q0 + r) * DIM + h * HD + kc * 8;
        cp16(so,          Qh + g);
        cp16(so + 32768,  Ql + g);
    }
    atc_stage(Kh, Kl, Vth, Vtl, t0 + ATC_STAGE,     0,  kvh, tid); // buf0 (+Q)
    atc_stage(Kh, Kl, Vth, Vtl, t0 + 2 * ATC_STAGE, 64, kvh, tid); // buf1

    float of[64];
#pragma unroll
    for (int j = 0; j < 64; ++j) of[j] = 0.0f;

    for (int t = 0; t < nt; ++t) {
        const int j0 = t * BKT;
        if (t >= 1 && t + 1 < nt)
            atc_stage(Kh, Kl, Vth, Vtl, t0 + ATC_STAGE * (1 + ((t + 1) & 1)),
                      (t + 1) * BKT, kvh, tid);
        if (t + 1 < nt) asm volatile("cp.async.wait_group 1;");
        else            asm volatile("cp.async.wait_group 0;");
        FENCE_ASYNC();
        __syncthreads();

        const uint32_t sbase = t0 + ATC_STAGE * (1 + (t & 1));

        // ---- S = Q @ K^T (3-term) -> TMEM[0,64) ----
        if (tid == 0) {
            TCGEN05_FENCE_AFTER();
#pragma unroll
            for (int c = 0; c < 2; ++c) {
                uint64_t dQh = MAKE_SMEM_DESC(t0 + c * 16384);
                uint64_t dQl = MAKE_SMEM_DESC(t0 + 32768 + c * 16384);
                uint64_t dKh = MAKE_SMEM_DESC(sbase + c * 8192);
                uint64_t dKl = MAKE_SMEM_DESC(sbase + 16384 + c * 8192);
#pragma unroll
                for (int s = 0; s < 4; ++s) {
                    umma_f16_ss(tmem, dQh + 2 * s, dKh + 2 * s, IDESC_S,
                                (c == 0 && s == 0) ? 0u : 1u);
                    umma_f16_ss(tmem, dQh + 2 * s, dKl + 2 * s, IDESC_S, 1u);
                    umma_f16_ss(tmem, dQl + 2 * s, dKh + 2 * s, IDESC_S, 1u);
                }
            }
            TCGEN05_COMMIT(mbs);
        }
        MBARRIER_WAIT_PARITY(mbs, t & 1);
        TCGEN05_FENCE_AFTER();

        // ---- read S, softmax ----
        uint32_t sr[32];
        TCGEN05_LD_X32(sr, tmem + half * 32);
        TCGEN05_WAIT_LD();
        float sv[32];
#pragma unroll
        for (int j = 0; j < 32; ++j) sv[j] = __uint_as_float(sr[j]);
        if (t >= nt - 2) {
#pragma unroll
            for (int j = 0; j < 32; ++j)
                if (j0 + half * 32 + j > qrow) sv[j] = -1e30f;
        }
        float mymax = -1e30f;
#pragma unroll
        for (int j = 0; j < 32; ++j) mymax = fmaxf(mymax, sv[j]);
        red0[half * 128 + row] = mymax;
        __syncthreads();
        float mt = fmaxf(red0[row], red0[128 + row]);
        float mold = smm[row];
        float mn = fmaxf(mold, mt);
        float alpha = __expf(mold - mn);
        float mysum = 0.0f;
#pragma unroll
        for (int j = 0; j < 32; ++j) {
            sv[j] = __expf(sv[j] - mn);
            mysum += sv[j];
        }
        red1[half * 128 + row] = mysum;
        __syncthreads();
        if (half == 0) {
            sml[row] = sml[row] * alpha + red1[row] + red1[128 + row];
            smm[row] = mn;
        }

        // ---- pack P -> TMEM (hi at 64, lo at 96) ----
        uint32_t ph[16], pl[16];
#pragma unroll
        for (int j = 0; j < 16; ++j) {
            float a = sv[2 * j], b = sv[2 * j + 1];
            ph[j] = bpack(a, b);
            __nv_bfloat162 hv = *(__nv_bfloat162*)&ph[j];
            pl[j] = bpack(a - __bfloat162float(hv.x), b - __bfloat162float(hv.y));
        }
        uint32_t lo_off = (uint32_t)sp << 21;
        TCGEN05_ST_X16(tmem + 64 + half * 16 + lo_off, ph);
        TCGEN05_ST_X16(tmem + 96 + half * 16 + lo_off, pl);
        TCGEN05_WAIT_ST();
        TCGEN05_FENCE_BEFORE();
        __syncthreads();

        // ---- PV = P @ Vt (TS mode, 3-term) -> TMEM[128,256) ----
        if (tid == 0) {
            TCGEN05_FENCE_AFTER();
            uint64_t dVh = MAKE_SMEM_DESC(sbase + 32768);
            uint64_t dVl = MAKE_SMEM_DESC(sbase + 49152);
#pragma unroll
            for (int ks = 0; ks < 4; ++ks) {
                umma_f16_ts(tmem + 128, tmem + 64 + ks * 8, dVh + 2 * ks,
                            IDESC_PV, ks == 0 ? 0u : 1u);
                umma_f16_ts(tmem + 128, tmem + 64 + ks * 8, dVl + 2 * ks,
                            IDESC_PV, 1u);
                umma_f16_ts(tmem + 128, tmem + 96 + ks * 8, dVh + 2 * ks,
                            IDESC_PV, 1u);
            }
            TCGEN05_COMMIT(mbpv);
        }
        MBARRIER_WAIT_PARITY(mbpv, t & 1);
        TCGEN05_FENCE_AFTER();

        // ---- accumulate O in registers ----
        uint32_t pv[32];
        TCGEN05_LD_X32(pv, tmem + 128 + half * 64);
        TCGEN05_WAIT_LD();
#pragma unroll
        for (int j = 0; j < 32; ++j)
            of[j] = of[j] * alpha + __uint_as_float(pv[j]);
        TCGEN05_LD_X32(pv, tmem + 128 + half * 64 + 32);
        TCGEN05_WAIT_LD();
#pragma unroll
        for (int j = 0; j < 32; ++j)
            of[32 + j] = of[32 + j] * alpha + __uint_as_float(pv[j]);
    }

    // ---- normalize + bf16 hi/lo store ----
    float inv = 1.0f / sml[row];
#pragma unroll
    for (int j = 0; j < 32; ++j) {
        float a = of[2 * j] * inv, b = of[2 * j + 1] * inv;
        uint32_t hh = bpack(a, b);
        __nv_bfloat162 hv = *(__nv_bfloat162*)&hh;
        uint32_t ll = bpack(a - __bfloat162float(hv.x),
                            b - __bfloat162float(hv.y));
        long o = (long)qrow * DIM + h * HD + half * 64 + 2 * j;
        *(uint32_t*)&Oh[o] = hh;
        *(uint32_t*)&Ol[o] = ll;
    }
    __syncthreads();
    if (w == 0) TCGEN05_DEALLOC(tmem, 256);

#else
    // ======================= mma.sync fallback ===============================
    __nv_bfloat16* sma = (__nv_bfloat16*)smg_raw;
    __nv_bfloat16* sKh[2] = {sma + 0 * ATT_TS, sma + 1 * ATT_TS};
    __nv_bfloat16* sKl[2] = {sma + 2 * ATT_TS, sma + 3 * ATT_TS};
    __nv_bfloat16* sVh[2] = {sma + 4 * ATT_TS, sma + 5 * ATT_TS};
    __nv_bfloat16* sVl[2] = {sma + 6 * ATT_TS, sma + 7 * ATT_TS};

    const int g = lane >> 2;
    const int qq = lane & 3;
    const int r0 = q0 + w * 16 + g;
    const int r1 = r0 + 8;
    uint32_t qfh[8][4], qfl[8][4];
#pragma unroll
    for (int k = 0; k < 8; ++k) {
        int c = h * HD + k * 16 + qq * 2;
        qfh[k][0] = *(const uint32_t*)&Qh[(long)r0 * DIM + c];
        qfh[k][1] = *(const uint32_t*)&Qh[(long)r1 * DIM + c];
        qfh[k][2] = *(const uint32_t*)&Qh[(long)r0 * DIM + c + 8];
        qfh[k][3] = *(const uint32_t*)&Qh[(long)r1 * DIM + c + 8];
        qfl[k][0] = *(const uint32_t*)&Ql[(long)r0 * DIM + c];
        qfl[k][1] = *(const uint32_t*)&Ql[(long)r1 * DIM + c];
        qfl[k][2] = *(const uint32_t*)&Ql[(long)r0 * DIM + c + 8];
        qfl[k][3] = *(const uint32_t*)&Ql[(long)r1 * DIM + c + 8];
    }

    float of[16][4];
#pragma unroll
    for (int i = 0; i < 16; ++i)
#pragma unroll
        for (int j = 0; j < 4; ++j) of[i][j] = 0.0f;
    float m0 = -1e30f, m1 = -1e30f, l0 = 0.0f, l1 = 0.0f;

    attn_issue_fb(Kh, Kl, Vh, Vl, sKh[0], sKl[0], sVh[0], sVl[0], 0, kvh, tid);

    for (int t = 0; t < nt; ++t) {
        if (t + 1 < nt) {
            int bb = (t + 1) & 1;
            attn_issue_fb(Kh, Kl, Vh, Vl, sKh[bb], sKl[bb], sVh[bb], sVl[bb],
                          (t + 1) * BKT, kvh, tid);
            asm volatile("cp.async.wait_group 1;");
        } else {
            asm volatile("cp.async.wait_group 0;");
        }
        __syncthreads();
        const int buf = t & 1;
        const int j0 = t * BKT;

        float sc[8][4];
#pragma unroll
        for (int i = 0; i < 8; ++i)
#pragma unroll
            for (int j = 0; j < 4; ++j) sc[i][j] = 0.0f;

#pragma unroll
        for (int k = 0; k < 8; ++k) {
#pragma unroll
            for (int np = 0; np < 4; ++np) {
                int brow = np * 16 + (lane & 7) + ((lane >> 4) << 3);
                int bcol = k * 16 + (((lane >> 3) & 1) << 3);
                uint32_t bh[4], bl[4];
                ldsm4(bh[0], bh[1], bh[2], bh[3],
                      smaddr(sKh[buf] + brow * PADK + bcol));
                ldsm4(bl[0], bl[1], bl[2], bl[3],
                      smaddr(sKl[buf] + brow * PADK + bcol));
#pragma unroll
                for (int hf = 0; hf < 2; ++hf) {
                    int nf = np * 2 + hf;
                    mma16816(sc[nf], qfh[k], bh[hf * 2], bh[hf * 2 + 1]);
                    mma16816(sc[nf], qfh[k], bl[hf * 2], bl[hf * 2 + 1]);
                    mma16816(sc[nf], qfl[k], bh[hf * 2], bh[hf * 2 + 1]);
                }
            }
        }

        if (t >= nt - 2) {
#pragma unroll
            for (int nf = 0; nf < 8; ++nf) {
                int cb = j0 + nf * 8 + qq * 2;
                if (cb > r0)     sc[nf][0] = -1e30f;
                if (cb + 1 > r0) sc[nf][1] = -1e30f;
                if (cb > r1)     sc[nf][2] = -1e30f;
                if (cb + 1 > r1) sc[nf][3] = -1e30f;
            }
        }

        float mt0 = -1e30f, mt1 = -1e30f;
#pragma unroll
        for (int nf = 0; nf < 8; ++nf) {
            mt0 = fmaxf(mt0, fmaxf(sc[nf][0], sc[nf][1]));
            mt1 = fmaxf(mt1, fmaxf(sc[nf][2], sc[nf][3]));
        }
        mt0 = fmaxf(mt0, __shfl_xor_sync(0xffffffff, mt0, 1));
        mt0 = fmaxf(mt0, __shfl_xor_sync(0xffffffff, mt0, 2));
        mt1 = fmaxf(mt1, __shfl_xor_sync(0xffffffff, mt1, 1));
        mt1 = fmaxf(mt1, __shfl_xor_sync(0xffffffff, mt1, 2));
        float mn0 = fmaxf(m0, mt0), mn1 = fmaxf(m1, mt1);
        float a0 = __expf(m0 - mn0), a1 = __expf(m1 - mn1);
        m0 = mn0; m1 = mn1;

        float rs0 = 0.0f, rs1 = 0.0f;
#pragma unroll
        for (int nf = 0; nf < 8; ++nf) {
            sc[nf][0] = __expf(sc[nf][0] - mn0); rs0 += sc[nf][0];
            sc[nf][1] = __expf(sc[nf][1] - mn0); rs0 += sc[nf][1];
            sc[nf][2] = __expf(sc[nf][2] - mn1); rs1 += sc[nf][2];
            sc[nf][3] = __expf(sc[nf][3] - mn1); rs1 += sc[nf][3];
        }
        rs0 += __shfl_xor_sync(0xffffffff, rs0, 1);
        rs0 += __shfl_xor_sync(0xffffffff, rs0, 2);
        rs1 += __shfl_xor_sync(0xffffffff, rs1, 1);
        rs1 += __shfl_xor_sync(0xffffffff, rs1, 2);
        l0 = l0 * a0 + rs0;
        l1 = l1 * a1 + rs1;

#pragma unroll
        for (int nf = 0; nf < 16; ++nf) {
            of[nf][0] *= a0; of[nf][1] *= a0;
            of[nf][2] *= a1; of[nf][3] *= a1;
        }

#pragma unroll
        for (int ks = 0; ks < 4; ++ks) {
            uint32_t ph[4], pl[4];
            {
                float s00 = sc[2 * ks][0],     s01 = sc[2 * ks][1];
                float s02 = sc[2 * ks][2],     s03 = sc[2 * ks][3];
                float s10 = sc[2 * ks + 1][0], s11 = sc[2 * ks + 1][1];
                float s12 = sc[2 * ks + 1][2], s13 = sc[2 * ks + 1][3];
                ph[0] = bpack(s00, s01); ph[1] = bpack(s02, s03);
                ph[2] = bpack(s10, s11); ph[3] = bpack(s12, s13);
                __nv_bfloat162* hp;
                hp = (__nv_bfloat162*)&ph[0];
                pl[0] = bpack(s00 - __bfloat162float(hp->x), s01 - __bfloat162float(hp->y));
                hp = (__nv_bfloat162*)&ph[1];
                pl[1] = bpack(s02 - __bfloat162float(hp->x), s03 - __bfloat162float(hp->y));
                hp = (__nv_bfloat162*)&ph[2];
                pl[2] = bpack(s10 - __bfloat162float(hp->x), s11 - __bfloat162float(hp->y));
                hp = (__nv_bfloat162*)&ph[3];
                pl[3] = bpack(s12 - __bfloat162float(hp->x), s13 - __bfloat162float(hp->y));
            }
            int vrow = ks * 16 + (lane & 7) + (((lane >> 3) & 1) << 3);
#pragma unroll
            for (int nn = 0; nn < 8; ++nn) {
                int vcol = nn * 16 + ((lane >> 4) << 3);
                uint32_t vh[4], vl[4];
                ldsm4t(vh[0], vh[1], vh[2], vh[3],
                       smaddr(sVh[buf] + vrow * PADK + vcol));
                ldsm4t(vl[0], vl[1], vl[2], vl[3],
                       smaddr(sVl[buf] + vrow * PADK + vcol));
                mma16816(of[nn * 2], ph, vh[0], vh[1]);
                mma16816(of[nn * 2], ph, vl[0], vl[1]);
                mma16816(of[nn * 2], pl, vh[0], vh[1]);
                mma16816(of[nn * 2 + 1], ph, vh[2], vh[3]);
                mma16816(of[nn * 2 + 1], ph, vl[2], vl[3]);
                mma16816(of[nn * 2 + 1], pl, vh[2], vh[3]);
            }
        }
        __syncthreads();
    }

    float inv0 = 1.0f / l0, inv1 = 1.0f / l1;
#pragma unroll
    for (int nf = 0; nf < 16; ++nf) {
        int col = h * HD + nf * 8 + qq * 2;
        {
            float a = of[nf][0] * inv0, b = of[nf][1] * inv0;
            uint32_t hh = bpack(a, b);
            __nv_bfloat162 hv = *(__nv_bfloat162*)&hh;
            uint32_t ll = bpack(a - __bfloat162float(hv.x),
                                b - __bfloat162float(hv.y));
            *(uint32_t*)&Oh[(long)r0 * DIM + col] = hh;
            *(uint32_t*)&Ol[(long)r0 * DIM + col] = ll;
        }
        {
            float a = of[nf][2] * inv1, b = of[nf][3] * inv1;
            uint32_t hh = bpack(a, b);
            __nv_bfloat162 hv = *(__nv_bfloat162*)&hh;
            uint32_t ll = bpack(a - __bfloat162float(hv.x),
                                b - __bfloat162float(hv.y));
            *(uint32_t*)&Oh[(long)r1 * DIM + col] = hh;
            *(uint32_t*)&Ol[(long)r1 * DIM + col] = ll;
        }
    }
#endif
}

// ---------------------------------------------------------------------------
// Launcher
// ---------------------------------------------------------------------------
extern "C" void kernel_launch(void* const* d_in, const int* in_sizes, int n_in,
                              void* d_out, int out_size) {
    const float* x  = (const float*)d_in[0];
    const float* wq = (const float*)d_in[1];
    const float* wk = (const float*)d_in[2];
    const float* wv = (const float*)d_in[3];
    const float* wo = (const float*)d_in[4];
    const float* fc = (const float*)d_in[5];
    const float* fs = (const float*)d_in[6];
    float* out = (float*)d_out;

    float *Qp, *Kp, *Vp;
    cudaGetSymbolAddress((void**)&Qp, g_Q);
    cudaGetSymbolAddress((void**)&Kp, g_K);
    cudaGetSymbolAddress((void**)&Vp, g_V);

    __nv_bfloat16 *xh, *xl, *wqh, *wql, *wkh, *wkl, *wvh, *wvl, *woh, *wol, *oh, *ol;
    __nv_bfloat16 *qh, *ql, *kh, *kl, *vh, *vl, *vth, *vtl;
    cudaGetSymbolAddress((void**)&xh,  g_xh);  cudaGetSymbolAddress((void**)&xl,  g_xl);
    cudaGetSymbolAddress((void**)&wqh, g_wqh); cudaGetSymbolAddress((void**)&wql, g_wql);
    cudaGetSymbolAddress((void**)&wkh, g_wkh); cudaGetSymbolAddress((void**)&wkl, g_wkl);
    cudaGetSymbolAddress((void**)&wvh, g_wvh); cudaGetSymbolAddress((void**)&wvl, g_wvl);
    cudaGetSymbolAddress((void**)&woh, g_woh); cudaGetSymbolAddress((void**)&wol, g_wol);
    cudaGetSymbolAddress((void**)&oh,  g_oh);  cudaGetSymbolAddress((void**)&ol,  g_ol);
    cudaGetSymbolAddress((void**)&qh,  g_Qh);  cudaGetSymbolAddress((void**)&ql,  g_Ql);
    cudaGetSymbolAddress((void**)&kh,  g_Kh);  cudaGetSymbolAddress((void**)&kl,  g_Kl);
    cudaGetSymbolAddress((void**)&vh,  g_Vh);  cudaGetSymbolAddress((void**)&vl,  g_Vl);
    cudaGetSymbolAddress((void**)&vth, g_Vth); cudaGetSymbolAddress((void**)&vtl, g_Vtl);

    cudaFuncSetAttribute(gemm_tc,
                         cudaFuncAttributeMaxDynamicSharedMemorySize, GT_SMEM);
    int att_smem = ATC_SMEM > ATT_SMEM_FB ? ATC_SMEM : ATT_SMEM_FB;
    cudaFuncSetAttribute(attn_tc,
                         cudaFuncAttributeMaxDynamicSharedMemorySize, att_smem);

    auto launch_split = [](const float* in, __nv_bfloat16* hi, __nv_bfloat16* lo, int n) {
        int n4 = n / 4;
        split_bf16<<<(n4 + 255) / 256, 256>>>(in, hi, lo, n4);
    };
    launch_split(x,  xh,  xl,  SEQ * DIM);
    launch_split(wq, wqh, wql, DIM * DIM);
    launch_split(wk, wkh, wkl, KV_DIM * DIM);
    launch_split(wv, wvh, wvl, KV_DIM * DIM);
    launch_split(wo, woh, wol, DIM * DIM);

    // Projections
    gemm_tc<<<dim3(DIM / 256, SEQ / 128), 256, GT_SMEM>>>(
        xh, xl, wqh, wql, Qp, nullptr, nullptr, nullptr, SEQ, DIM, DIM);
    gemm_tc<<<dim3(2 * KV_DIM / 256, SEQ / 128), 256, GT_SMEM>>>(
        xh, xl, wkh, wkl, Kp, wvh, wvl, Vp, SEQ, KV_DIM, DIM);

    // RoPE + split; V split (fallback) + V transpose split (tcgen05 path)
    int qpairs = SEQ * NH * (HD / 2);
    int kpairs = SEQ * NKV * (HD / 2);
    rope_split<<<(qpairs + 255) / 256, 256>>>(Qp, qh, ql, fc, fs, NH, 0.08838834764831845f);
    rope_split<<<(kpairs + 255) / 256, 256>>>(Kp, kh, kl, fc, fs, NKV, 1.0f);
    launch_split(Vp, vh, vl, SEQ * KV_DIM);
    vt_split<<<dim3(SEQ / 32, KV_DIM / 32), dim3(32, 8)>>>(Vp, vth, vtl);

    // Flash attention (tcgen05) -> bf16 hi/lo output
    attn_tc<<<dim3(SEQ / BQT, NH), 256, att_smem>>>(
        qh, ql, kh, kl, vh, vl, vth, vtl, oh, ol);

    // Output projection
    gemm_tc<<<dim3(DIM / 256, SEQ / 128), 256, GT_SMEM>>>(
        oh, ol, woh, wol, out, nullptr, nullptr, nullptr, SEQ, DIM, DIM);
}